// round 5
// baseline (speedup 1.0000x reference)
#include <cuda_runtime.h>
#include <math.h>

// ---------------- problem constants ----------------
#define C_IN 576
#define HF   12
#define WF   20
#define NB   16
#define POS  240                  // HF*WF
#define M_TOT (NB*POS)            // 3840  (positions)
#define G_TOT (8*C_IN)            // 4608  (all heads' out channels)
#define K_TOT (C_IN*9)            // 5184  (reduction dim)

// ---------------- scratch (static device globals; no runtime alloc) ----------------
__device__ __align__(16) float g_B[(size_t)K_TOT * M_TOT];   // im2col  [K][M]  ~80 MB
__device__ __align__(16) float g_H[(size_t)G_TOT * M_TOT];   // silu(bn(conv)) [G][M] ~71 MB
__device__ float g_scale[G_TOT];
__device__ float g_shift[G_TOT];
__device__ __align__(16) float g_maps[14 * M_TOT];           // pre-activation maps
__device__ __align__(16) float g_cand[NB * 100 * 10];        // detection candidates

// ---------------- helpers ----------------
__device__ __forceinline__ float sigm(float x) { return 1.0f / (1.0f + expf(-x)); }
__device__ __forceinline__ float clipf(float x, float lo, float hi) { return fminf(fmaxf(x, lo), hi); }

__device__ __forceinline__ unsigned long long pack2(float lo, float hi) {
    unsigned long long r;
    asm("mov.b64 %0, {%1, %2};" : "=l"(r) : "r"(__float_as_uint(lo)), "r"(__float_as_uint(hi)));
    return r;
}
__device__ __forceinline__ void unpack2(unsigned long long v, float& lo, float& hi) {
    unsigned a, b;
    asm("mov.b64 {%0, %1}, %2;" : "=r"(a), "=r"(b) : "l"(v));
    lo = __uint_as_float(a); hi = __uint_as_float(b);
}
// packed dual fp32 FMA (FFMA2) — 2x fp32 throughput on sm_103a fma pipe
__device__ __forceinline__ void fma2(unsigned long long& acc, unsigned long long a, unsigned long long b) {
    asm("fma.rn.f32x2 %0, %1, %2, %0;" : "+l"(acc) : "l"(a), "l"(b));
}

// ---------------- kernel 1: global-average pool + linear + single_out ----------------
__global__ void single_kernel(const float* __restrict__ f,
                              const float* __restrict__ linW,
                              const float* __restrict__ linb,
                              float* __restrict__ out) {
    const int n = blockIdx.x;
    const int c = threadIdx.x;                 // 576 threads
    __shared__ float sf1[C_IN];
    __shared__ float slin[10];
    const float* p = f + ((size_t)n * C_IN + c) * POS;
    float s = 0.f;
    for (int i = 0; i < POS; i++) s += p[i];
    sf1[c] = s / 240.0f;
    __syncthreads();
    if (c < 10) {
        float a = linb[c];
        for (int k = 0; k < C_IN; k++) a += sf1[k] * linW[c * C_IN + k];
        slin[c] = a;
    }
    __syncthreads();
    if (c == 0) {
        const float eps = 1e-5f;
        float conf = clipf(sigm(slin[0]), eps, 1.0f - eps);
        int best = 0; float bv = slin[1];
        for (int i = 1; i < 5; i++) if (slin[1 + i] > bv) { bv = slin[1 + i]; best = i; }
        float dist = sigm(slin[6]) * 3.0f;
        float offv = tanhf(slin[7]);
        float sev  = clipf(sigm(slin[8]), eps, 1.0f - eps);
        float surf = clipf(sigm(slin[9]), eps, 1.0f - eps);
        float* o = out + n * 6;
        o[0] = conf; o[1] = (float)best; o[2] = dist; o[3] = offv; o[4] = sev; o[5] = surf;
    }
}

// ---------------- kernel 2: fold BN into per-channel affine ----------------
__global__ void bn_prep_kernel(const float* __restrict__ g, const float* __restrict__ b,
                               const float* __restrict__ m, const float* __restrict__ v) {
    int i = blockIdx.x * blockDim.x + threadIdx.x;
    if (i < G_TOT) {
        float sc = g[i] / sqrtf(v[i] + 1e-5f);
        g_scale[i] = sc;
        g_shift[i] = b[i] - m[i] * sc;
    }
}

// ---------------- kernel 3: im2col  B[k][m] ----------------
__global__ void im2col_kernel(const float* __restrict__ f) {
    const int k = blockIdx.x;                  // 5184 blocks
    const int ci = k / 9;
    const int tap = k - ci * 9;
    const int ky = tap / 3, kx = tap - ky * 3;
    float* Brow = g_B + (size_t)k * M_TOT;
    for (int m = threadIdx.x; m < M_TOT; m += blockDim.x) {
        int n = m / POS; int pm = m - n * POS;
        int y = pm / WF; int x = pm - y * WF;
        int yy = y + ky - 1, xx = x + kx - 1;
        float v = 0.f;
        if ((unsigned)yy < HF && (unsigned)xx < WF)
            v = f[(((size_t)n * C_IN + ci) * HF + yy) * WF + xx];
        Brow[m] = v;
    }
}

// ---------------- kernel 4: SGEMM (FFMA2) + BN + SiLU epilogue ----------------
// C[g][m] = sum_k w1[g][k] * B[k][m]; H = silu(C*scale + shift), stored g-major.
__global__ __launch_bounds__(256, 2) void gemm_kernel(const float* __restrict__ A) {
    __shared__ float As[2][8][128];
    __shared__ float Bs[2][8][128];
    const int tid = threadIdx.x;
    const int mBase = blockIdx.x * 128;
    const int gBase = blockIdx.y * 128;

    const int a_row = tid >> 1;
    const int a_col = (tid & 1) << 2;
    const int b_row = tid >> 5;
    const int b_col = (tid & 31) << 2;

    const float* Aptr = A + (size_t)(gBase + a_row) * K_TOT + a_col;
    const float* Bptr = g_B + (size_t)b_row * M_TOT + mBase + b_col;

    // prologue: stage tile 0
    {
        float4 la = *(const float4*)Aptr;
        float4 lb = *(const float4*)Bptr;
        As[0][a_col + 0][a_row] = la.x;
        As[0][a_col + 1][a_row] = la.y;
        As[0][a_col + 2][a_row] = la.z;
        As[0][a_col + 3][a_row] = la.w;
        *(float4*)&Bs[0][b_row][b_col] = lb;
    }
    __syncthreads();

    const int tx = tid & 15;
    const int ty = tid >> 4;

    unsigned long long acc[8][4];
#pragma unroll
    for (int i = 0; i < 8; i++)
#pragma unroll
        for (int j = 0; j < 4; j++) acc[i][j] = 0ULL;

    const int KT = K_TOT / 8;  // 648
    for (int kt = 0; kt < KT; kt++) {
        const int buf = kt & 1;
        float4 na, nb;
        const bool more = (kt + 1 < KT);
        if (more) {
            na = *(const float4*)(Aptr + (kt + 1) * 8);
            nb = *(const float4*)(Bptr + (size_t)(kt + 1) * 8 * M_TOT);
        }
#pragma unroll
        for (int kk = 0; kk < 8; kk++) {
            float4 a0 = *(const float4*)&As[buf][kk][ty * 4];
            float4 a1 = *(const float4*)&As[buf][kk][64 + ty * 4];
            float4 b0 = *(const float4*)&Bs[buf][kk][tx * 4];
            float4 b1 = *(const float4*)&Bs[buf][kk][64 + tx * 4];
            unsigned long long bp[4];
            bp[0] = pack2(b0.x, b0.y); bp[1] = pack2(b0.z, b0.w);
            bp[2] = pack2(b1.x, b1.y); bp[3] = pack2(b1.z, b1.w);
            float av[8] = {a0.x, a0.y, a0.z, a0.w, a1.x, a1.y, a1.z, a1.w};
#pragma unroll
            for (int i = 0; i < 8; i++) {
                unsigned long long ap = pack2(av[i], av[i]);
#pragma unroll
                for (int j = 0; j < 4; j++) fma2(acc[i][j], ap, bp[j]);
            }
        }
        if (more) {
            const int nbuf = buf ^ 1;
            As[nbuf][a_col + 0][a_row] = na.x;
            As[nbuf][a_col + 1][a_row] = na.y;
            As[nbuf][a_col + 2][a_row] = na.z;
            As[nbuf][a_col + 3][a_row] = na.w;
            *(float4*)&Bs[nbuf][b_row][b_col] = nb;
        }
        __syncthreads();
    }

    // epilogue: BN affine + SiLU, store H[g][m]
#pragma unroll
    for (int i = 0; i < 8; i++) {
        const int r = (i < 4) ? (ty * 4 + i) : (64 + ty * 4 + i - 4);
        const int g = gBase + r;
        const float scv = g_scale[g];
        const float shv = g_shift[g];
        float vals[8];
#pragma unroll
        for (int j = 0; j < 4; j++) {
            float lo, hi; unpack2(acc[i][j], lo, hi);
            vals[2 * j] = lo; vals[2 * j + 1] = hi;
        }
#pragma unroll
        for (int q = 0; q < 8; q++) {
            float v = vals[q] * scv + shv;
            vals[q] = v / (1.0f + expf(-v));          // silu
        }
        float* hp = g_H + (size_t)g * M_TOT + mBase;
        *(float4*)(hp + tx * 4)      = make_float4(vals[0], vals[1], vals[2], vals[3]);
        *(float4*)(hp + 64 + tx * 4) = make_float4(vals[4], vals[5], vals[6], vals[7]);
    }
}

// ---------------- kernel 5: w2 reduction -> 14 maps (pre-activation, +b2) ----------------
__global__ void maps_kernel(const float* __restrict__ w2, const float* __restrict__ b2) {
    __shared__ float sw2[14 * C_IN];
    const int t = threadIdx.x;                 // 128
    for (int i = t; i < 14 * C_IN; i += 128) sw2[i] = w2[i];
    __syncthreads();
    const int m = blockIdx.x * 128 + t;
    float acc[14];
#pragma unroll
    for (int o = 0; o < 14; o++) acc[o] = 0.f;
    const int OFFS_[9] = {0, 5, 6, 8, 10, 11, 12, 13, 14};
    const float* hp = g_H + m;
#pragma unroll
    for (int head = 0; head < 8; head++) {
        const int o0 = OFFS_[head], o1 = OFFS_[head + 1];
        for (int c = 0; c < C_IN; c++) {
            float v = hp[(size_t)(head * C_IN + c) * M_TOT];
#pragma unroll
            for (int o = o0; o < o1; o++) acc[o] += sw2[o * C_IN + c] * v;
        }
    }
#pragma unroll
    for (int o = 0; o < 14; o++) g_maps[o * M_TOT + m] = acc[o] + b2[o];
}

// ---------------- kernel 6: per-(n,class) top-20 + candidate fields ----------------
__global__ void topk_kernel() {
    const int n = blockIdx.x / 5, j = blockIdx.x % 5;
    const int t = threadIdx.x;                 // 256
    __shared__ float sc[256];
    __shared__ float rv[256];
    __shared__ int   ri[256];
    __shared__ float selv[20];
    __shared__ int   seli[20];

    float s = -1e30f;
    if (t < POS) {
        float heat = sigm(g_maps[j * M_TOT + n * POS + t]);
        float cf   = sigm(g_maps[5 * M_TOT + n * POS + t]);
        s = heat * cf;
    }
    sc[t] = s;
    __syncthreads();

    for (int r = 0; r < 20; r++) {
        rv[t] = sc[t]; ri[t] = t;
        __syncthreads();
#pragma unroll
        for (int off = 128; off > 0; off >>= 1) {
            if (t < off) {
                float v2 = rv[t + off]; int i2 = ri[t + off];
                if (v2 > rv[t] || (v2 == rv[t] && i2 < ri[t])) { rv[t] = v2; ri[t] = i2; }
            }
            __syncthreads();
        }
        if (t == 0) { selv[r] = rv[0]; seli[r] = ri[0]; sc[ri[0]] = -1e30f; }
        __syncthreads();
    }

    if (t < 20) {
        const int idx = seli[t];
        const float score = selv[t];
        const int base = n * POS + idx;
        float gx = sigm(g_maps[6  * M_TOT + base]);
        float gy = sigm(g_maps[7  * M_TOT + base]);
        float gw = sigm(g_maps[8  * M_TOT + base]);
        float gh = sigm(g_maps[9  * M_TOT + base]);
        float gd = sigm(g_maps[10 * M_TOT + base]) * 3.0f;
        float go = tanhf(g_maps[11 * M_TOT + base]);
        float gs = sigm(g_maps[12 * M_TOT + base]);
        float gf = sigm(g_maps[13 * M_TOT + base]);
        float xi = (float)(idx % WF);
        float yi = (float)(idx / WF);
        float cx = clipf(xi + gx, 0.f, (float)(WF - 1)) * 32.0f;   // 640/20
        float cy = clipf(yi + gy, 0.f, (float)(HF - 1)) * 32.0f;   // 384/12
        float bw = clipf(gw, 0.f, 1.f) * 640.0f;
        float bh = clipf(gh, 0.f, 1.f) * 384.0f;
        float x1 = clipf(cx - bw * 0.5f, 0.f, 639.0f);
        float y1 = clipf(cy - bh * 0.5f, 0.f, 383.0f);
        float x2 = clipf(cx + bw * 0.5f, 0.f, 639.0f);
        float y2 = clipf(cy + bh * 0.5f, 0.f, 383.0f);
        float* row = g_cand + ((size_t)n * 100 + j * 20 + t) * 10;
        row[0] = score; row[1] = (float)j; row[2] = gd; row[3] = go; row[4] = gs;
        row[5] = gf; row[6] = x1; row[7] = y1; row[8] = x2; row[9] = y2;
    }
}

// ---------------- kernel 7: stable sort by dist (rank trick) -> dets_out ----------------
__global__ void sort_out_kernel(float* __restrict__ out) {
    const int n = blockIdx.x;
    const int t = threadIdx.x;                 // 128
    __shared__ float d[100];
    if (t < 100) d[t] = g_cand[((size_t)n * 100 + t) * 10 + 2];
    __syncthreads();
    if (t < 100) {
        float di = d[t];
        int rank = 0;
        for (int k = 0; k < 100; k++) {
            float dk = d[k];
            rank += (dk < di) || (dk == di && k < t);   // stable ascending
        }
        if (rank < 20) {
            float* dst = out + 96 + ((size_t)n * 20 + rank) * 10;
            const float* src = g_cand + ((size_t)n * 100 + t) * 10;
#pragma unroll
            for (int q = 0; q < 10; q++) dst[q] = src[q];
        }
    }
}

// ---------------- launch ----------------
extern "C" void kernel_launch(void* const* d_in, const int* in_sizes, int n_in,
                              void* d_out, int out_size) {
    const float* f    = (const float*)d_in[0];
    const float* w1   = (const float*)d_in[1];
    const float* bng  = (const float*)d_in[2];
    const float* bnb  = (const float*)d_in[3];
    const float* bnm  = (const float*)d_in[4];
    const float* bnv  = (const float*)d_in[5];
    const float* w2   = (const float*)d_in[6];
    const float* b2   = (const float*)d_in[7];
    const float* linW = (const float*)d_in[8];
    const float* linb = (const float*)d_in[9];
    float* out = (float*)d_out;

    single_kernel<<<NB, C_IN>>>(f, linW, linb, out);
    bn_prep_kernel<<<(G_TOT + 255) / 256, 256>>>(bng, bnb, bnm, bnv);
    im2col_kernel<<<K_TOT, 256>>>(f);
    dim3 gg(M_TOT / 128, G_TOT / 128);
    gemm_kernel<<<gg, 256>>>(w1);
    maps_kernel<<<M_TOT / 128, 128>>>(w2, b2);
    topk_kernel<<<NB * 5, 256>>>();
    sort_out_kernel<<<NB, 128>>>(out);
}

// round 6
// speedup vs baseline: 1.1961x; 1.1961x over previous
#include <cuda_runtime.h>
#include <math.h>

// ---------------- problem constants ----------------
#define C_IN 576
#define HF   12
#define WF   20
#define NB   16
#define POS  240                  // HF*WF
#define M_TOT (NB*POS)            // 3840  (positions)
#define G_TOT (8*C_IN)            // 4608  (all heads' out channels)
#define K_TOT (C_IN*9)            // 5184  (reduction dim)
#define KTILE 16
#define KT_ITERS (K_TOT/KTILE)    // 324

// ---------------- scratch (static device globals; no runtime alloc) ----------------
__device__ __align__(16) float g_B[(size_t)K_TOT * M_TOT];   // im2col  [K][M]  ~80 MB
__device__ __align__(16) float g_H[(size_t)G_TOT * M_TOT];   // silu(bn(conv)) [G][M] ~71 MB
__device__ float g_scale[G_TOT];
__device__ float g_shift[G_TOT];
__device__ __align__(16) float g_maps[14 * M_TOT];           // pre-activation maps
__device__ __align__(16) float g_cand[NB * 100 * 10];        // detection candidates

// ---------------- helpers ----------------
__device__ __forceinline__ float sigm(float x) { return 1.0f / (1.0f + expf(-x)); }
__device__ __forceinline__ float clipf(float x, float lo, float hi) { return fminf(fmaxf(x, lo), hi); }

__device__ __forceinline__ unsigned long long pack2(float lo, float hi) {
    unsigned long long r;
    asm("mov.b64 %0, {%1, %2};" : "=l"(r) : "r"(__float_as_uint(lo)), "r"(__float_as_uint(hi)));
    return r;
}
__device__ __forceinline__ void unpack2(unsigned long long v, float& lo, float& hi) {
    unsigned a, b;
    asm("mov.b64 {%0, %1}, %2;" : "=r"(a), "=r"(b) : "l"(v));
    lo = __uint_as_float(a); hi = __uint_as_float(b);
}
// packed dual fp32 FMA (FFMA2) — 2x fp32 throughput on sm_103a fma pipe
__device__ __forceinline__ void fma2(unsigned long long& acc, unsigned long long a, unsigned long long b) {
    asm("fma.rn.f32x2 %0, %1, %2, %0;" : "+l"(acc) : "l"(a), "l"(b));
}

// ---------------- kernel 1: global-average pool + linear + single_out ----------------
__global__ void single_kernel(const float* __restrict__ f,
                              const float* __restrict__ linW,
                              const float* __restrict__ linb,
                              float* __restrict__ out) {
    const int n = blockIdx.x;
    const int c = threadIdx.x;                 // 576 threads
    __shared__ float sf1[C_IN];
    __shared__ float slin[10];
    const float* p = f + ((size_t)n * C_IN + c) * POS;
    float s = 0.f;
#pragma unroll 4
    for (int i = 0; i < POS; i++) s += p[i];
    sf1[c] = s / 240.0f;
    __syncthreads();
    if (c < 10) {
        float a = linb[c];
        for (int k = 0; k < C_IN; k++) a += sf1[k] * linW[c * C_IN + k];
        slin[c] = a;
    }
    __syncthreads();
    if (c == 0) {
        const float eps = 1e-5f;
        float conf = clipf(sigm(slin[0]), eps, 1.0f - eps);
        int best = 0; float bv = slin[1];
        for (int i = 1; i < 5; i++) if (slin[1 + i] > bv) { bv = slin[1 + i]; best = i; }
        float dist = sigm(slin[6]) * 3.0f;
        float offv = tanhf(slin[7]);
        float sev  = clipf(sigm(slin[8]), eps, 1.0f - eps);
        float surf = clipf(sigm(slin[9]), eps, 1.0f - eps);
        float* o = out + n * 6;
        o[0] = conf; o[1] = (float)best; o[2] = dist; o[3] = offv; o[4] = sev; o[5] = surf;
    }
}

// ---------------- kernel 2: fold BN into per-channel affine ----------------
__global__ void bn_prep_kernel(const float* __restrict__ g, const float* __restrict__ b,
                               const float* __restrict__ m, const float* __restrict__ v) {
    int i = blockIdx.x * blockDim.x + threadIdx.x;
    if (i < G_TOT) {
        float sc = g[i] / sqrtf(v[i] + 1e-5f);
        g_scale[i] = sc;
        g_shift[i] = b[i] - m[i] * sc;
    }
}

// ---------------- kernel 3: im2col  B[k][m] ----------------
__global__ void im2col_kernel(const float* __restrict__ f) {
    const int k = blockIdx.x;                  // 5184 blocks
    const int ci = k / 9;
    const int tap = k - ci * 9;
    const int ky = tap / 3, kx = tap - ky * 3;
    float* Brow = g_B + (size_t)k * M_TOT;
    for (int m = threadIdx.x; m < M_TOT; m += blockDim.x) {
        int n = m / POS; int pm = m - n * POS;
        int y = pm / WF; int x = pm - y * WF;
        int yy = y + ky - 1, xx = x + kx - 1;
        float v = 0.f;
        if ((unsigned)yy < HF && (unsigned)xx < WF)
            v = f[(((size_t)n * C_IN + ci) * HF + yy) * WF + xx];
        Brow[m] = v;
    }
}

// ---------------- kernel 4: SGEMM (FFMA2) + BN + SiLU epilogue ----------------
// C[g][m] = sum_k w1[g][k] * B[k][m]; H = silu(C*scale + shift), stored g-major.
// KTILE=16 (half the barriers), padded smem (132), B operand read as raw 64-bit pairs.
__global__ __launch_bounds__(256, 2) void gemm_kernel(const float* __restrict__ A) {
    __shared__ float As[2][KTILE][132];
    __shared__ float Bs[2][KTILE][132];
    const int tid = threadIdx.x;
    const int mBase = blockIdx.x * 128;
    const int gBase = blockIdx.y * 128;

    // staging coords
    const int a_row  = tid >> 1;               // 0..127  (g within tile)
    const int a_colb = (tid & 1) << 3;         // 0 or 8  (k within tile)
    const int b_row  = tid >> 4;               // 0..15   (k within tile)
    const int b_colb = (tid & 15) << 3;        // 0..120  (m within tile)

    const float* Aptr = A + (size_t)(gBase + a_row) * K_TOT + a_colb;
    const float* Bptr = g_B + (size_t)b_row * M_TOT + mBase + b_colb;

    // prologue: stage tile 0
    {
        float4 la0 = *(const float4*)(Aptr);
        float4 la1 = *(const float4*)(Aptr + 4);
        float4 lb0 = *(const float4*)(Bptr);
        float4 lb1 = *(const float4*)(Bptr + 4);
        As[0][a_colb + 0][a_row] = la0.x;
        As[0][a_colb + 1][a_row] = la0.y;
        As[0][a_colb + 2][a_row] = la0.z;
        As[0][a_colb + 3][a_row] = la0.w;
        As[0][a_colb + 4][a_row] = la1.x;
        As[0][a_colb + 5][a_row] = la1.y;
        As[0][a_colb + 6][a_row] = la1.z;
        As[0][a_colb + 7][a_row] = la1.w;
        *(float4*)&Bs[0][b_row][b_colb]     = lb0;
        *(float4*)&Bs[0][b_row][b_colb + 4] = lb1;
    }
    __syncthreads();

    const int tx = tid & 15;
    const int ty = tid >> 4;

    unsigned long long acc[8][4];
#pragma unroll
    for (int i = 0; i < 8; i++)
#pragma unroll
        for (int j = 0; j < 4; j++) acc[i][j] = 0ULL;

    for (int kt = 0; kt < KT_ITERS; kt++) {
        const int buf = kt & 1;
        float4 na0, na1, nb0, nb1;
        const bool more = (kt + 1 < KT_ITERS);
        if (more) {
            const float* ap = Aptr + (kt + 1) * KTILE;
            const float* bp = Bptr + (size_t)(kt + 1) * KTILE * M_TOT;
            na0 = *(const float4*)(ap);
            na1 = *(const float4*)(ap + 4);
            nb0 = *(const float4*)(bp);
            nb1 = *(const float4*)(bp + 4);
        }
#pragma unroll
        for (int kk = 0; kk < KTILE; kk++) {
            // B operand: adjacent m-pairs are already packed in shared memory
            const unsigned long long* bq0 = (const unsigned long long*)&Bs[buf][kk][tx * 4];
            const unsigned long long* bq1 = (const unsigned long long*)&Bs[buf][kk][64 + tx * 4];
            unsigned long long bp0 = bq0[0], bp1 = bq0[1];
            unsigned long long bp2 = bq1[0], bp3 = bq1[1];
            float4 a0 = *(const float4*)&As[buf][kk][ty * 4];
            float4 a1 = *(const float4*)&As[buf][kk][64 + ty * 4];
            float av[8] = {a0.x, a0.y, a0.z, a0.w, a1.x, a1.y, a1.z, a1.w};
#pragma unroll
            for (int i = 0; i < 8; i++) {
                unsigned long long ap = pack2(av[i], av[i]);
                fma2(acc[i][0], ap, bp0);
                fma2(acc[i][1], ap, bp1);
                fma2(acc[i][2], ap, bp2);
                fma2(acc[i][3], ap, bp3);
            }
        }
        if (more) {
            const int nbuf = buf ^ 1;
            As[nbuf][a_colb + 0][a_row] = na0.x;
            As[nbuf][a_colb + 1][a_row] = na0.y;
            As[nbuf][a_colb + 2][a_row] = na0.z;
            As[nbuf][a_colb + 3][a_row] = na0.w;
            As[nbuf][a_colb + 4][a_row] = na1.x;
            As[nbuf][a_colb + 5][a_row] = na1.y;
            As[nbuf][a_colb + 6][a_row] = na1.z;
            As[nbuf][a_colb + 7][a_row] = na1.w;
            *(float4*)&Bs[nbuf][b_row][b_colb]     = nb0;
            *(float4*)&Bs[nbuf][b_row][b_colb + 4] = nb1;
        }
        __syncthreads();
    }

    // epilogue: BN affine + SiLU, store H[g][m]
#pragma unroll
    for (int i = 0; i < 8; i++) {
        const int r = (i < 4) ? (ty * 4 + i) : (64 + ty * 4 + i - 4);
        const int g = gBase + r;
        const float scv = g_scale[g];
        const float shv = g_shift[g];
        float vals[8];
#pragma unroll
        for (int j = 0; j < 4; j++) {
            float lo, hi; unpack2(acc[i][j], lo, hi);
            vals[2 * j] = lo; vals[2 * j + 1] = hi;
        }
#pragma unroll
        for (int q = 0; q < 8; q++) {
            float v = vals[q] * scv + shv;
            vals[q] = v / (1.0f + expf(-v));          // silu
        }
        float* hp = g_H + (size_t)g * M_TOT + mBase;
        *(float4*)(hp + tx * 4)      = make_float4(vals[0], vals[1], vals[2], vals[3]);
        *(float4*)(hp + 64 + tx * 4) = make_float4(vals[4], vals[5], vals[6], vals[7]);
    }
}

// ---------------- kernel 5: w2 reduction -> 14 maps (pre-activation, +b2) ----------------
// grid (M_TOT/128, 8): heads write disjoint output channels -> no conflicts, 8x parallelism.
__constant__ int c_offs[9] = {0, 5, 6, 8, 10, 11, 12, 13, 14};
__global__ void maps_kernel(const float* __restrict__ w2, const float* __restrict__ b2) {
    const int head = blockIdx.y;
    const int o0 = c_offs[head], o1 = c_offs[head + 1];
    const int no = o1 - o0;                    // 1..5
    __shared__ float sw2[5][C_IN];
    const int t = threadIdx.x;                 // 128
    for (int i = t; i < no * C_IN; i += 128) sw2[i / C_IN][i % C_IN] = w2[o0 * C_IN + i];
    __syncthreads();
    const int m = blockIdx.x * 128 + t;
    float acc[5] = {0.f, 0.f, 0.f, 0.f, 0.f};
    const float* hp = g_H + (size_t)head * C_IN * M_TOT + m;
#pragma unroll 4
    for (int c = 0; c < C_IN; c++) {
        float v = hp[(size_t)c * M_TOT];
#pragma unroll
        for (int o = 0; o < 5; o++)
            if (o < no) acc[o] += sw2[o][c] * v;
    }
#pragma unroll
    for (int o = 0; o < 5; o++)
        if (o < no) g_maps[(o0 + o) * M_TOT + m] = acc[o] + b2[o0 + o];
}

// ---------------- kernel 6: per-(n,class) top-20 + candidate fields ----------------
__global__ void topk_kernel() {
    const int n = blockIdx.x / 5, j = blockIdx.x % 5;
    const int t = threadIdx.x;                 // 256
    __shared__ float sc[256];
    __shared__ float rv[256];
    __shared__ int   ri[256];
    __shared__ float selv[20];
    __shared__ int   seli[20];

    float s = -1e30f;
    if (t < POS) {
        float heat = sigm(g_maps[j * M_TOT + n * POS + t]);
        float cf   = sigm(g_maps[5 * M_TOT + n * POS + t]);
        s = heat * cf;
    }
    sc[t] = s;
    __syncthreads();

    for (int r = 0; r < 20; r++) {
        rv[t] = sc[t]; ri[t] = t;
        __syncthreads();
#pragma unroll
        for (int off = 128; off > 0; off >>= 1) {
            if (t < off) {
                float v2 = rv[t + off]; int i2 = ri[t + off];
                if (v2 > rv[t] || (v2 == rv[t] && i2 < ri[t])) { rv[t] = v2; ri[t] = i2; }
            }
            __syncthreads();
        }
        if (t == 0) { selv[r] = rv[0]; seli[r] = ri[0]; sc[ri[0]] = -1e30f; }
        __syncthreads();
    }

    if (t < 20) {
        const int idx = seli[t];
        const float score = selv[t];
        const int base = n * POS + idx;
        float gx = sigm(g_maps[6  * M_TOT + base]);
        float gy = sigm(g_maps[7  * M_TOT + base]);
        float gw = sigm(g_maps[8  * M_TOT + base]);
        float gh = sigm(g_maps[9  * M_TOT + base]);
        float gd = sigm(g_maps[10 * M_TOT + base]) * 3.0f;
        float go = tanhf(g_maps[11 * M_TOT + base]);
        float gs = sigm(g_maps[12 * M_TOT + base]);
        float gf = sigm(g_maps[13 * M_TOT + base]);
        float xi = (float)(idx % WF);
        float yi = (float)(idx / WF);
        float cx = clipf(xi + gx, 0.f, (float)(WF - 1)) * 32.0f;   // 640/20
        float cy = clipf(yi + gy, 0.f, (float)(HF - 1)) * 32.0f;   // 384/12
        float bw = clipf(gw, 0.f, 1.f) * 640.0f;
        float bh = clipf(gh, 0.f, 1.f) * 384.0f;
        float x1 = clipf(cx - bw * 0.5f, 0.f, 639.0f);
        float y1 = clipf(cy - bh * 0.5f, 0.f, 383.0f);
        float x2 = clipf(cx + bw * 0.5f, 0.f, 639.0f);
        float y2 = clipf(cy + bh * 0.5f, 0.f, 383.0f);
        float* row = g_cand + ((size_t)n * 100 + j * 20 + t) * 10;
        row[0] = score; row[1] = (float)j; row[2] = gd; row[3] = go; row[4] = gs;
        row[5] = gf; row[6] = x1; row[7] = y1; row[8] = x2; row[9] = y2;
    }
}

// ---------------- kernel 7: stable sort by dist (rank trick) -> dets_out ----------------
__global__ void sort_out_kernel(float* __restrict__ out) {
    const int n = blockIdx.x;
    const int t = threadIdx.x;                 // 128
    __shared__ float d[100];
    if (t < 100) d[t] = g_cand[((size_t)n * 100 + t) * 10 + 2];
    __syncthreads();
    if (t < 100) {
        float di = d[t];
        int rank = 0;
        for (int k = 0; k < 100; k++) {
            float dk = d[k];
            rank += (dk < di) || (dk == di && k < t);   // stable ascending
        }
        if (rank < 20) {
            float* dst = out + 96 + ((size_t)n * 20 + rank) * 10;
            const float* src = g_cand + ((size_t)n * 100 + t) * 10;
#pragma unroll
            for (int q = 0; q < 10; q++) dst[q] = src[q];
        }
    }
}

// ---------------- launch ----------------
extern "C" void kernel_launch(void* const* d_in, const int* in_sizes, int n_in,
                              void* d_out, int out_size) {
    const float* f    = (const float*)d_in[0];
    const float* w1   = (const float*)d_in[1];
    const float* bng  = (const float*)d_in[2];
    const float* bnb  = (const float*)d_in[3];
    const float* bnm  = (const float*)d_in[4];
    const float* bnv  = (const float*)d_in[5];
    const float* w2   = (const float*)d_in[6];
    const float* b2   = (const float*)d_in[7];
    const float* linW = (const float*)d_in[8];
    const float* linb = (const float*)d_in[9];
    float* out = (float*)d_out;

    single_kernel<<<NB, C_IN>>>(f, linW, linb, out);
    bn_prep_kernel<<<(G_TOT + 255) / 256, 256>>>(bng, bnb, bnm, bnv);
    im2col_kernel<<<K_TOT, 256>>>(f);
    dim3 gg(M_TOT / 128, G_TOT / 128);
    gemm_kernel<<<gg, 256>>>(w1);
    dim3 mg(M_TOT / 128, 8);
    maps_kernel<<<mg, 128>>>(w2, b2);
    topk_kernel<<<NB * 5, 256>>>();
    sort_out_kernel<<<NB, 128>>>(out);
}

// round 9
// speedup vs baseline: 1.9607x; 1.6392x over previous
#include <cuda_runtime.h>
#include <math.h>
#include <cstdint>

// ---------------- problem constants ----------------
#define C_IN 576
#define HF   12
#define WF   20
#define NB   16
#define POS  240
#define M_TOT 3840                 // positions (16*240)
#define G_TOT 4608                 // 8*576 output channels
#define TY_T 6                     // winograd tile rows  (12/2)
#define TX_T 10                    // winograd tile cols  (20/2)
#define NT   60                    // tiles per image
#define J_TOT (NB*NT)              // 960
#define J_PAD 1024
#define KTILE 16
#define KT_ITERS (C_IN/KTILE)      // 36

// ---------------- scratch (static device globals; zero-initialized) ----------------
__device__ __align__(16) float g_U[(size_t)16 * G_TOT * C_IN];   // transformed weights ~170MB
__device__ __align__(16) float g_V[(size_t)16 * C_IN * J_PAD];   // transformed inputs  ~38MB (pad cols stay 0)
__device__ __align__(16) float g_M[(size_t)16 * G_TOT * J_PAD];  // GEMM results       ~302MB
__device__ __align__(16) float g_H[(size_t)G_TOT * M_TOT];       // silu(bn(conv))     ~71MB
__device__ float g_scale[G_TOT];
__device__ float g_shift[G_TOT];
__device__ __align__(16) float g_maps[14 * M_TOT];
__device__ __align__(16) float g_cand[NB * 100 * 10];

// ---------------- helpers ----------------
__device__ __forceinline__ float sigm(float x) { return 1.0f / (1.0f + expf(-x)); }
__device__ __forceinline__ float clipf(float x, float lo, float hi) { return fminf(fmaxf(x, lo), hi); }

__device__ __forceinline__ unsigned long long pack2(float lo, float hi) {
    unsigned long long r;
    asm("mov.b64 %0, {%1, %2};" : "=l"(r) : "r"(__float_as_uint(lo)), "r"(__float_as_uint(hi)));
    return r;
}
__device__ __forceinline__ void unpack2(unsigned long long v, float& lo, float& hi) {
    unsigned a, b;
    asm("mov.b64 {%0, %1}, %2;" : "=r"(a), "=r"(b) : "l"(v));
    lo = __uint_as_float(a); hi = __uint_as_float(b);
}
// packed dual fp32 FMA (FFMA2) — 2x fp32 throughput on sm_103a fma pipe
__device__ __forceinline__ void fma2(unsigned long long& acc, unsigned long long a, unsigned long long b) {
    asm("fma.rn.f32x2 %0, %1, %2, %0;" : "+l"(acc) : "l"(a), "l"(b));
}

// ---------------- kernel: BN fold ----------------
__global__ void bn_prep_kernel(const float* __restrict__ g, const float* __restrict__ b,
                               const float* __restrict__ m, const float* __restrict__ v) {
    int i = blockIdx.x * blockDim.x + threadIdx.x;
    if (i < G_TOT) {
        float sc = g[i] / sqrtf(v[i] + 1e-5f);
        g_scale[i] = sc;
        g_shift[i] = b[i] - m[i] * sc;
    }
}

// ---------------- kernel: winograd weight transform  U = G g G^T ----------------
__global__ void wg_transform_kernel(const float* __restrict__ w1) {
    int idx = blockIdx.x * blockDim.x + threadIdx.x;      // 4608*576
    int co = idx / C_IN, ci = idx % C_IN;
    const float* w = w1 + (size_t)idx * 9;                // (co*C+ci)*9
    float g0 = w[0], g1 = w[1], g2 = w[2];
    float g3 = w[3], g4 = w[4], g5 = w[5];
    float g6 = w[6], g7 = w[7], g8 = w[8];
    float t00 = g0, t01 = g1, t02 = g2;
    float t10 = 0.5f * (g0 + g3 + g6), t11 = 0.5f * (g1 + g4 + g7), t12 = 0.5f * (g2 + g5 + g8);
    float t20 = 0.5f * (g0 - g3 + g6), t21 = 0.5f * (g1 - g4 + g7), t22 = 0.5f * (g2 - g5 + g8);
    float t30 = g6, t31 = g7, t32 = g8;
    float U[16];
    #define WROW(r, a, b, c) \
        U[r*4+0] = (a); U[r*4+1] = 0.5f*((a)+(b)+(c)); U[r*4+2] = 0.5f*((a)-(b)+(c)); U[r*4+3] = (c);
    WROW(0, t00, t01, t02) WROW(1, t10, t11, t12) WROW(2, t20, t21, t22) WROW(3, t30, t31, t32)
    #undef WROW
    size_t plane = (size_t)G_TOT * C_IN;
    size_t off = (size_t)co * C_IN + ci;
#pragma unroll
    for (int uv = 0; uv < 16; uv++) g_U[uv * plane + off] = U[uv];
}

// ---------------- kernel: winograd input transform  V = B^T d B ----------------
__global__ void in_transform_kernel(const float* __restrict__ f) {
    int idx = blockIdx.x * blockDim.x + threadIdx.x;      // 16*576*60
    int n = idx / (C_IN * NT);
    int r = idx % (C_IN * NT);
    int ci = r / NT, t = r % NT;
    int ty = t / TX_T, tx = t % TX_T;
    const float* fp = f + ((size_t)n * C_IN + ci) * POS;
    float X[4][4];
#pragma unroll
    for (int a = 0; a < 4; a++) {
        int iy = 2 * ty - 1 + a;
#pragma unroll
        for (int b = 0; b < 4; b++) {
            int ix = 2 * tx - 1 + b;
            X[a][b] = ((unsigned)iy < HF && (unsigned)ix < WF) ? fp[iy * WF + ix] : 0.f;
        }
    }
    float T[4][4];
#pragma unroll
    for (int b = 0; b < 4; b++) {
        T[0][b] = X[0][b] - X[2][b];
        T[1][b] = X[1][b] + X[2][b];
        T[2][b] = X[2][b] - X[1][b];
        T[3][b] = X[1][b] - X[3][b];
    }
    size_t plane = (size_t)C_IN * J_PAD;
    size_t off = (size_t)ci * J_PAD + n * NT + t;
#pragma unroll
    for (int a = 0; a < 4; a++) {
        float v0 = T[a][0] - T[a][2];
        float v1 = T[a][1] + T[a][2];
        float v2 = T[a][2] - T[a][1];
        float v3 = T[a][1] - T[a][3];
        g_V[(a * 4 + 0) * plane + off] = v0;
        g_V[(a * 4 + 1) * plane + off] = v1;
        g_V[(a * 4 + 2) * plane + off] = v2;
        g_V[(a * 4 + 3) * plane + off] = v3;
    }
}

// ---------------- kernel: batched FFMA2 GEMM  M_uv = U_uv x V_uv ----------------
// grid (J_PAD/128, G_TOT/128, 16).  A tile stored DUPLICATED in smem.
// As row: 128 cos duplicated = 256 floats (1024B); second co-half at +128 floats.
#define AS_OFF(b) ((b) * 16384)
#define BS_OFF(b) (32768 + (b) * 8192)
__global__ __launch_bounds__(256, 2) void gemm_kernel() {
    extern __shared__ char smem[];
    const int tid = threadIdx.x;
    const int jb = blockIdx.x * 128;
    const int gb = blockIdx.y * 128;
    const int uv = blockIdx.z;

    const float* A0 = g_U + ((size_t)uv * G_TOT + gb) * C_IN;       // rows: co, k contig
    const float* B0 = g_V + (size_t)uv * C_IN * J_PAD + jb;         // rows: k,  j contig

    const int a_co = tid >> 1;                 // 0..127
    const int a_k0 = (tid & 1) << 3;           // 0 or 8
    const int b_k  = tid >> 4;                 // 0..15
    const int b_j0 = (tid & 15) << 3;          // 0..120

    const float* Aptr = A0 + (size_t)a_co * C_IN + a_k0;
    const float* Bptr = B0 + (size_t)b_k * J_PAD + b_j0;

    // prologue: stage tile 0
    {
        float4 la0 = *(const float4*)(Aptr);
        float4 la1 = *(const float4*)(Aptr + 4);
        float4 lb0 = *(const float4*)(Bptr);
        float4 lb1 = *(const float4*)(Bptr + 4);
        float av[8] = {la0.x, la0.y, la0.z, la0.w, la1.x, la1.y, la1.z, la1.w};
#pragma unroll
        for (int i = 0; i < 8; i++) {
            float* asr = (float*)(smem + AS_OFF(0) + (a_k0 + i) * 1024);
            *(unsigned long long*)(asr + 2 * a_co) = pack2(av[i], av[i]);
        }
        float* bsr = (float*)(smem + BS_OFF(0) + b_k * 512);
        *(float4*)(bsr + b_j0)     = lb0;
        *(float4*)(bsr + b_j0 + 4) = lb1;
    }
    __syncthreads();

    const int tx = tid & 15;
    const int ty = tid >> 4;

    unsigned long long acc[8][4];
#pragma unroll
    for (int i = 0; i < 8; i++)
#pragma unroll
        for (int j = 0; j < 4; j++) acc[i][j] = 0ULL;

    for (int kt = 0; kt < KT_ITERS; kt++) {
        const int buf = kt & 1;
        float4 na0, na1, nb0, nb1;
        const bool more = (kt + 1 < KT_ITERS);
        if (more) {
            const float* ap = Aptr + (kt + 1) * KTILE;
            const float* bp = Bptr + (size_t)(kt + 1) * KTILE * J_PAD;
            na0 = *(const float4*)(ap);
            na1 = *(const float4*)(ap + 4);
            nb0 = *(const float4*)(bp);
            nb1 = *(const float4*)(bp + 4);
        }
#pragma unroll
        for (int kk = 0; kk < KTILE; kk++) {
            const float* asr = (const float*)(smem + AS_OFF(buf) + kk * 1024);
            const float* bsr = (const float*)(smem + BS_OFF(buf) + kk * 512);
            ulonglong2 aA = *(const ulonglong2*)(asr + 8 * ty);          // cos 4ty..4ty+1 (dup)
            ulonglong2 aB = *(const ulonglong2*)(asr + 8 * ty + 4);      // cos 4ty+2..4ty+3
            ulonglong2 aC = *(const ulonglong2*)(asr + 128 + 8 * ty);    // cos 64+4ty..  (FIXED: +128 floats)
            ulonglong2 aD = *(const ulonglong2*)(asr + 128 + 8 * ty + 4);
            ulonglong2 b0 = *(const ulonglong2*)(bsr + 4 * tx);          // js tx*4..+3
            ulonglong2 b1 = *(const ulonglong2*)(bsr + 64 + 4 * tx);     // js 64+tx*4..
            unsigned long long ap8[8] = {aA.x, aA.y, aB.x, aB.y, aC.x, aC.y, aD.x, aD.y};
            unsigned long long bp4[4] = {b0.x, b0.y, b1.x, b1.y};
#pragma unroll
            for (int i = 0; i < 8; i++) {
                fma2(acc[i][0], ap8[i], bp4[0]);
                fma2(acc[i][1], ap8[i], bp4[1]);
                fma2(acc[i][2], ap8[i], bp4[2]);
                fma2(acc[i][3], ap8[i], bp4[3]);
            }
        }
        if (more) {
            const int nbuf = buf ^ 1;
            float av[8] = {na0.x, na0.y, na0.z, na0.w, na1.x, na1.y, na1.z, na1.w};
#pragma unroll
            for (int i = 0; i < 8; i++) {
                float* asr = (float*)(smem + AS_OFF(nbuf) + (a_k0 + i) * 1024);
                *(unsigned long long*)(asr + 2 * a_co) = pack2(av[i], av[i]);
            }
            float* bsr = (float*)(smem + BS_OFF(nbuf) + b_k * 512);
            *(float4*)(bsr + b_j0)     = nb0;
            *(float4*)(bsr + b_j0 + 4) = nb1;
        }
        __syncthreads();
    }

    // epilogue: raw store to g_M[uv][co][j]
#pragma unroll
    for (int i = 0; i < 8; i++) {
        const int r = (i < 4) ? (4 * ty + i) : (64 + 4 * ty + (i - 4));
        float* mp = g_M + ((size_t)uv * G_TOT + gb + r) * J_PAD + jb;
        float v0, v1, v2, v3;
        unpack2(acc[i][0], v0, v1); unpack2(acc[i][1], v2, v3);
        *(float4*)(mp + tx * 4) = make_float4(v0, v1, v2, v3);
        unpack2(acc[i][2], v0, v1); unpack2(acc[i][3], v2, v3);
        *(float4*)(mp + 64 + tx * 4) = make_float4(v0, v1, v2, v3);
    }
}

// ---------------- kernel: inverse transform + BN + SiLU -> g_H[co][m] ----------------
__global__ void out_transform_kernel() {
    int idx = blockIdx.x * blockDim.x + threadIdx.x;      // 4608*960
    int co = idx / J_TOT, j = idx % J_TOT;
    int n = j / NT, t = j % NT;
    int ty = t / TX_T, tx = t % TX_T;
    size_t plane = (size_t)G_TOT * J_PAD;
    const float* mp = g_M + (size_t)co * J_PAD + j;
    float m[16];
#pragma unroll
    for (int uv = 0; uv < 16; uv++) m[uv] = mp[uv * plane];
    float t0[4], t1[4];
#pragma unroll
    for (int b = 0; b < 4; b++) {
        t0[b] = m[0 * 4 + b] + m[1 * 4 + b] + m[2 * 4 + b];
        t1[b] = m[1 * 4 + b] - m[2 * 4 + b] - m[3 * 4 + b];
    }
    float y00 = t0[0] + t0[1] + t0[2];
    float y01 = t0[1] - t0[2] - t0[3];
    float y10 = t1[0] + t1[1] + t1[2];
    float y11 = t1[1] - t1[2] - t1[3];
    const float sc = g_scale[co], sh = g_shift[co];
    float* hp = g_H + (size_t)co * M_TOT + n * POS + (2 * ty) * WF + 2 * tx;
    float v;
    v = y00 * sc + sh; hp[0]      = v / (1.0f + expf(-v));
    v = y01 * sc + sh; hp[1]      = v / (1.0f + expf(-v));
    v = y10 * sc + sh; hp[WF]     = v / (1.0f + expf(-v));
    v = y11 * sc + sh; hp[WF + 1] = v / (1.0f + expf(-v));
}

// ---------------- kernel 1: global-average pool + linear + single_out ----------------
__global__ void single_kernel(const float* __restrict__ f,
                              const float* __restrict__ linW,
                              const float* __restrict__ linb,
                              float* __restrict__ out) {
    const int n = blockIdx.x;
    const int c = threadIdx.x;                 // 576
    __shared__ float sf1[C_IN];
    __shared__ float slin[10];
    const float* p = f + ((size_t)n * C_IN + c) * POS;
    float s = 0.f;
#pragma unroll 4
    for (int i = 0; i < POS; i++) s += p[i];
    sf1[c] = s / 240.0f;
    __syncthreads();
    if (c < 10) {
        float a = linb[c];
        for (int k = 0; k < C_IN; k++) a += sf1[k] * linW[c * C_IN + k];
        slin[c] = a;
    }
    __syncthreads();
    if (c == 0) {
        const float eps = 1e-5f;
        float conf = clipf(sigm(slin[0]), eps, 1.0f - eps);
        int best = 0; float bv = slin[1];
        for (int i = 1; i < 5; i++) if (slin[1 + i] > bv) { bv = slin[1 + i]; best = i; }
        float dist = sigm(slin[6]) * 3.0f;
        float offv = tanhf(slin[7]);
        float sev  = clipf(sigm(slin[8]), eps, 1.0f - eps);
        float surf = clipf(sigm(slin[9]), eps, 1.0f - eps);
        float* o = out + n * 6;
        o[0] = conf; o[1] = (float)best; o[2] = dist; o[3] = offv; o[4] = sev; o[5] = surf;
    }
}

// ---------------- kernel 5: w2 reduction -> 14 maps ----------------
__constant__ int c_offs[9] = {0, 5, 6, 8, 10, 11, 12, 13, 14};
__global__ void maps_kernel(const float* __restrict__ w2, const float* __restrict__ b2) {
    const int head = blockIdx.y;
    const int o0 = c_offs[head], o1 = c_offs[head + 1];
    const int no = o1 - o0;
    __shared__ float sw2[5][C_IN];
    const int t = threadIdx.x;                 // 128
    for (int i = t; i < no * C_IN; i += 128) sw2[i / C_IN][i % C_IN] = w2[o0 * C_IN + i];
    __syncthreads();
    const int m = blockIdx.x * 128 + t;
    float acc[5] = {0.f, 0.f, 0.f, 0.f, 0.f};
    const float* hp = g_H + (size_t)head * C_IN * M_TOT + m;
#pragma unroll 4
    for (int c = 0; c < C_IN; c++) {
        float v = hp[(size_t)c * M_TOT];
#pragma unroll
        for (int o = 0; o < 5; o++)
            if (o < no) acc[o] += sw2[o][c] * v;
    }
#pragma unroll
    for (int o = 0; o < 5; o++)
        if (o < no) g_maps[(o0 + o) * M_TOT + m] = acc[o] + b2[o0 + o];
}

// ---------------- kernel 6: per-(n,class) top-20 ----------------
__global__ void topk_kernel() {
    const int n = blockIdx.x / 5, j = blockIdx.x % 5;
    const int t = threadIdx.x;                 // 256
    __shared__ float sc[256];
    __shared__ float rv[256];
    __shared__ int   ri[256];
    __shared__ float selv[20];
    __shared__ int   seli[20];

    float s = -1e30f;
    if (t < POS) {
        float heat = sigm(g_maps[j * M_TOT + n * POS + t]);
        float cf   = sigm(g_maps[5 * M_TOT + n * POS + t]);
        s = heat * cf;
    }
    sc[t] = s;
    __syncthreads();

    for (int r = 0; r < 20; r++) {
        rv[t] = sc[t]; ri[t] = t;
        __syncthreads();
#pragma unroll
        for (int off = 128; off > 0; off >>= 1) {
            if (t < off) {
                float v2 = rv[t + off]; int i2 = ri[t + off];
                if (v2 > rv[t] || (v2 == rv[t] && i2 < ri[t])) { rv[t] = v2; ri[t] = i2; }
            }
            __syncthreads();
        }
        if (t == 0) { selv[r] = rv[0]; seli[r] = ri[0]; sc[ri[0]] = -1e30f; }
        __syncthreads();
    }

    if (t < 20) {
        const int idx = seli[t];
        const float score = selv[t];
        const int base = n * POS + idx;
        float gx = sigm(g_maps[6  * M_TOT + base]);
        float gy = sigm(g_maps[7  * M_TOT + base]);
        float gw = sigm(g_maps[8  * M_TOT + base]);
        float gh = sigm(g_maps[9  * M_TOT + base]);
        float gd = sigm(g_maps[10 * M_TOT + base]) * 3.0f;
        float go = tanhf(g_maps[11 * M_TOT + base]);
        float gs = sigm(g_maps[12 * M_TOT + base]);
        float gf = sigm(g_maps[13 * M_TOT + base]);
        float xi = (float)(idx % WF);
        float yi = (float)(idx / WF);
        float cx = clipf(xi + gx, 0.f, (float)(WF - 1)) * 32.0f;
        float cy = clipf(yi + gy, 0.f, (float)(HF - 1)) * 32.0f;
        float bw = clipf(gw, 0.f, 1.f) * 640.0f;
        float bh = clipf(gh, 0.f, 1.f) * 384.0f;
        float x1 = clipf(cx - bw * 0.5f, 0.f, 639.0f);
        float y1 = clipf(cy - bh * 0.5f, 0.f, 383.0f);
        float x2 = clipf(cx + bw * 0.5f, 0.f, 639.0f);
        float y2 = clipf(cy + bh * 0.5f, 0.f, 383.0f);
        float* row = g_cand + ((size_t)n * 100 + j * 20 + t) * 10;
        row[0] = score; row[1] = (float)j; row[2] = gd; row[3] = go; row[4] = gs;
        row[5] = gf; row[6] = x1; row[7] = y1; row[8] = x2; row[9] = y2;
    }
}

// ---------------- kernel 7: stable sort by dist -> dets_out ----------------
__global__ void sort_out_kernel(float* __restrict__ out) {
    const int n = blockIdx.x;
    const int t = threadIdx.x;                 // 128
    __shared__ float d[100];
    if (t < 100) d[t] = g_cand[((size_t)n * 100 + t) * 10 + 2];
    __syncthreads();
    if (t < 100) {
        float di = d[t];
        int rank = 0;
        for (int k = 0; k < 100; k++) {
            float dk = d[k];
            rank += (dk < di) || (dk == di && k < t);
        }
        if (rank < 20) {
            float* dst = out + 96 + ((size_t)n * 20 + rank) * 10;
            const float* src = g_cand + ((size_t)n * 100 + t) * 10;
#pragma unroll
            for (int q = 0; q < 10; q++) dst[q] = src[q];
        }
    }
}

// ---------------- launch ----------------
extern "C" void kernel_launch(void* const* d_in, const int* in_sizes, int n_in,
                              void* d_out, int out_size) {
    const float* f    = (const float*)d_in[0];
    const float* w1   = (const float*)d_in[1];
    const float* bng  = (const float*)d_in[2];
    const float* bnb  = (const float*)d_in[3];
    const float* bnm  = (const float*)d_in[4];
    const float* bnv  = (const float*)d_in[5];
    const float* w2   = (const float*)d_in[6];
    const float* b2   = (const float*)d_in[7];
    const float* linW = (const float*)d_in[8];
    const float* linb = (const float*)d_in[9];
    float* out = (float*)d_out;

    single_kernel<<<NB, C_IN>>>(f, linW, linb, out);
    bn_prep_kernel<<<(G_TOT + 255) / 256, 256>>>(bng, bnb, bnm, bnv);
    wg_transform_kernel<<<(G_TOT * C_IN) / 256, 256>>>(w1);           // 10368 blocks
    in_transform_kernel<<<(NB * C_IN * NT) / 256, 256>>>(f);          // 2160 blocks
    dim3 gg(J_PAD / 128, G_TOT / 128, 16);                            // (8, 36, 16)
    gemm_kernel<<<gg, 256, 49152>>>();
    out_transform_kernel<<<(G_TOT * J_TOT) / 256, 256>>>();           // 17280 blocks
    dim3 mg(M_TOT / 128, 8);
    maps_kernel<<<mg, 128>>>(w2, b2);
    topk_kernel<<<NB * 5, 256>>>();
    sort_out_kernel<<<NB, 128>>>(out);
}

// round 11
// speedup vs baseline: 3.0472x; 1.5541x over previous
#include <cuda_runtime.h>
#include <math.h>
#include <cstdint>

// ---------------- problem constants ----------------
#define C_IN 576
#define HF   12
#define WF   20
#define NB   16
#define POS  240
#define M_TOT 3840                 // positions (16*240)
#define G_TOT 4608                 // 8*576 output channels
#define TY_T 3                     // winograd F(4,3) tile rows  (12/4)
#define TX_T 5                     // winograd F(4,3) tile cols  (20/4)
#define NT   15                    // tiles per image
#define J_TOT (NB*NT)              // 240
#define J_PAD 256
#define NUV  36                    // 6x6 transform plane count
#define KTILE 16
#define KT_ITERS (C_IN/KTILE)      // 36

// ---------------- scratch (static device globals; zero-initialized) ----------------
__device__ __align__(16) float g_U[(size_t)NUV * G_TOT * C_IN];   // transformed weights ~382MB
__device__ __align__(16) float g_V[(size_t)NUV * C_IN * J_PAD];   // transformed inputs  ~21MB (pad cols stay 0)
__device__ __align__(16) float g_M[(size_t)NUV * G_TOT * J_PAD];  // GEMM results       ~170MB
__device__ __align__(16) float g_H[(size_t)G_TOT * M_TOT];        // silu(bn(conv))     ~71MB
__device__ float g_scale[G_TOT];
__device__ float g_shift[G_TOT];
__device__ __align__(16) float g_maps[14 * M_TOT];
__device__ __align__(16) float g_cand[NB * 100 * 10];

// ---------------- helpers ----------------
__device__ __forceinline__ float sigm(float x) { return 1.0f / (1.0f + expf(-x)); }
__device__ __forceinline__ float clipf(float x, float lo, float hi) { return fminf(fmaxf(x, lo), hi); }

__device__ __forceinline__ unsigned long long pack2(float lo, float hi) {
    unsigned long long r;
    asm("mov.b64 %0, {%1, %2};" : "=l"(r) : "r"(__float_as_uint(lo)), "r"(__float_as_uint(hi)));
    return r;
}
__device__ __forceinline__ void unpack2(unsigned long long v, float& lo, float& hi) {
    unsigned a, b;
    asm("mov.b64 {%0, %1}, %2;" : "=r"(a), "=r"(b) : "l"(v));
    lo = __uint_as_float(a); hi = __uint_as_float(b);
}
// packed dual fp32 FMA (FFMA2) — 2x fp32 throughput on sm_103a fma pipe
__device__ __forceinline__ void fma2(unsigned long long& acc, unsigned long long a, unsigned long long b) {
    asm("fma.rn.f32x2 %0, %1, %2, %0;" : "+l"(acc) : "l"(a), "l"(b));
}

// ---------------- kernel: BN fold ----------------
__global__ void bn_prep_kernel(const float* __restrict__ g, const float* __restrict__ b,
                               const float* __restrict__ m, const float* __restrict__ v) {
    int i = blockIdx.x * blockDim.x + threadIdx.x;
    if (i < G_TOT) {
        float sc = g[i] / sqrtf(v[i] + 1e-5f);
        g_scale[i] = sc;
        g_shift[i] = b[i] - m[i] * sc;
    }
}

// F(4,3) G-row combo applied to a 3-vector (a,b,c) -> 6 outputs
#define GCOMBO(out, a, b, c) \
    out[0] = 0.25f * (a); \
    out[1] = -(1.0f/6.0f) * ((a) + (b) + (c)); \
    out[2] = (1.0f/6.0f) * (-(a) + (b) - (c)); \
    out[3] = (1.0f/24.0f) * (a) + (1.0f/12.0f) * (b) + (1.0f/6.0f) * (c); \
    out[4] = (1.0f/24.0f) * (a) - (1.0f/12.0f) * (b) + (1.0f/6.0f) * (c); \
    out[5] = (c);

// ---------------- kernel: winograd F(4,3) weight transform  U = G g G^T ----------------
__global__ void wg_transform_kernel(const float* __restrict__ w1) {
    int idx = blockIdx.x * blockDim.x + threadIdx.x;      // 4608*576
    int co = idx / C_IN, ci = idx % C_IN;
    const float* w = w1 + (size_t)idx * 9;                // (co*C+ci)*9, rows ky
    // T = G g : 6x3
    float T[6][3];
    {
        float col[6];
#pragma unroll
        for (int c = 0; c < 3; c++) {
            GCOMBO(col, w[c], w[3 + c], w[6 + c]);
#pragma unroll
            for (int r = 0; r < 6; r++) T[r][c] = col[r];
        }
    }
    // U = T G^T : each row (a,b,c) -> 6 outputs
    size_t plane = (size_t)G_TOT * C_IN;
    size_t off = (size_t)co * C_IN + ci;
#pragma unroll
    for (int r = 0; r < 6; r++) {
        float u[6];
        GCOMBO(u, T[r][0], T[r][1], T[r][2]);
#pragma unroll
        for (int c = 0; c < 6; c++) g_U[(size_t)(r * 6 + c) * plane + off] = u[c];
    }
}

// F(4,3) B^T-row combo applied to a 6-vector -> 6 outputs
#define BCOMBO(out, x0, x1, x2, x3, x4, x5) \
    out[0] = 4.0f*(x0) - 5.0f*(x2) + (x4); \
    out[1] = -4.0f*(x1) - 4.0f*(x2) + (x3) + (x4); \
    out[2] =  4.0f*(x1) - 4.0f*(x2) - (x3) + (x4); \
    out[3] = -2.0f*(x1) - (x2) + 2.0f*(x3) + (x4); \
    out[4] =  2.0f*(x1) - (x2) - 2.0f*(x3) + (x4); \
    out[5] =  4.0f*(x1) - 5.0f*(x3) + (x5);

// ---------------- kernel: winograd input transform  V = B^T d B ----------------
__global__ void in_transform_kernel(const float* __restrict__ f) {
    int idx = blockIdx.x * blockDim.x + threadIdx.x;      // 16*576*15
    if (idx >= NB * C_IN * NT) return;
    int n = idx / (C_IN * NT);
    int r = idx % (C_IN * NT);
    int ci = r / NT, t = r % NT;
    int ty = t / TX_T, tx = t % TX_T;
    const float* fp = f + ((size_t)n * C_IN + ci) * POS;
    float X[6][6];
#pragma unroll
    for (int a = 0; a < 6; a++) {
        int iy = 4 * ty - 1 + a;
#pragma unroll
        for (int b = 0; b < 6; b++) {
            int ix = 4 * tx - 1 + b;
            X[a][b] = ((unsigned)iy < HF && (unsigned)ix < WF) ? fp[iy * WF + ix] : 0.f;
        }
    }
    // T = B^T X
    float T[6][6];
    {
        float col[6];
#pragma unroll
        for (int b = 0; b < 6; b++) {
            BCOMBO(col, X[0][b], X[1][b], X[2][b], X[3][b], X[4][b], X[5][b]);
#pragma unroll
            for (int a = 0; a < 6; a++) T[a][b] = col[a];
        }
    }
    // V = T B
    size_t plane = (size_t)C_IN * J_PAD;
    size_t off = (size_t)ci * J_PAD + n * NT + t;
#pragma unroll
    for (int a = 0; a < 6; a++) {
        float v[6];
        BCOMBO(v, T[a][0], T[a][1], T[a][2], T[a][3], T[a][4], T[a][5]);
#pragma unroll
        for (int b = 0; b < 6; b++) g_V[(size_t)(a * 6 + b) * plane + off] = v[b];
    }
}

// ---------------- kernel: batched FFMA2 GEMM  M_uv = U_uv x V_uv ----------------
// grid (J_PAD/128, G_TOT/128, 36).  A tile stored DUPLICATED in smem.
// As row: 128 cos duplicated = 256 floats (1024B); second co-half at +128 floats.
#define AS_OFF(b) ((b) * 16384)
#define BS_OFF(b) (32768 + (b) * 8192)
__global__ __launch_bounds__(256, 2) void gemm_kernel() {
    extern __shared__ char smem[];
    const int tid = threadIdx.x;
    const int jb = blockIdx.x * 128;
    const int gb = blockIdx.y * 128;
    const int uv = blockIdx.z;

    const float* A0 = g_U + ((size_t)uv * G_TOT + gb) * C_IN;       // rows: co, k contig
    const float* B0 = g_V + (size_t)uv * C_IN * J_PAD + jb;         // rows: k,  j contig

    const int a_co = tid >> 1;                 // 0..127
    const int a_k0 = (tid & 1) << 3;           // 0 or 8
    const int b_k  = tid >> 4;                 // 0..15
    const int b_j0 = (tid & 15) << 3;          // 0..120

    const float* Aptr = A0 + (size_t)a_co * C_IN + a_k0;
    const float* Bptr = B0 + (size_t)b_k * J_PAD + b_j0;

    // prologue: stage tile 0
    {
        float4 la0 = *(const float4*)(Aptr);
        float4 la1 = *(const float4*)(Aptr + 4);
        float4 lb0 = *(const float4*)(Bptr);
        float4 lb1 = *(const float4*)(Bptr + 4);
        float av[8] = {la0.x, la0.y, la0.z, la0.w, la1.x, la1.y, la1.z, la1.w};
#pragma unroll
        for (int i = 0; i < 8; i++) {
            float* asr = (float*)(smem + AS_OFF(0) + (a_k0 + i) * 1024);
            *(unsigned long long*)(asr + 2 * a_co) = pack2(av[i], av[i]);
        }
        float* bsr = (float*)(smem + BS_OFF(0) + b_k * 512);
        *(float4*)(bsr + b_j0)     = lb0;
        *(float4*)(bsr + b_j0 + 4) = lb1;
    }
    __syncthreads();

    const int tx = tid & 15;
    const int ty = tid >> 4;

    unsigned long long acc[8][4];
#pragma unroll
    for (int i = 0; i < 8; i++)
#pragma unroll
        for (int j = 0; j < 4; j++) acc[i][j] = 0ULL;

    for (int kt = 0; kt < KT_ITERS; kt++) {
        const int buf = kt & 1;
        float4 na0, na1, nb0, nb1;
        const bool more = (kt + 1 < KT_ITERS);
        if (more) {
            const float* ap = Aptr + (kt + 1) * KTILE;
            const float* bp = Bptr + (size_t)(kt + 1) * KTILE * J_PAD;
            na0 = *(const float4*)(ap);
            na1 = *(const float4*)(ap + 4);
            nb0 = *(const float4*)(bp);
            nb1 = *(const float4*)(bp + 4);
        }
#pragma unroll
        for (int kk = 0; kk < KTILE; kk++) {
            const float* asr = (const float*)(smem + AS_OFF(buf) + kk * 1024);
            const float* bsr = (const float*)(smem + BS_OFF(buf) + kk * 512);
            ulonglong2 aA = *(const ulonglong2*)(asr + 8 * ty);          // cos 4ty..4ty+1 (dup)
            ulonglong2 aB = *(const ulonglong2*)(asr + 8 * ty + 4);      // cos 4ty+2..4ty+3
            ulonglong2 aC = *(const ulonglong2*)(asr + 128 + 8 * ty);    // cos 64+4ty..
            ulonglong2 aD = *(const ulonglong2*)(asr + 128 + 8 * ty + 4);
            ulonglong2 b0 = *(const ulonglong2*)(bsr + 4 * tx);          // js tx*4..+3
            ulonglong2 b1 = *(const ulonglong2*)(bsr + 64 + 4 * tx);     // js 64+tx*4..
            unsigned long long ap8[8] = {aA.x, aA.y, aB.x, aB.y, aC.x, aC.y, aD.x, aD.y};
            unsigned long long bp4[4] = {b0.x, b0.y, b1.x, b1.y};
#pragma unroll
            for (int i = 0; i < 8; i++) {
                fma2(acc[i][0], ap8[i], bp4[0]);
                fma2(acc[i][1], ap8[i], bp4[1]);
                fma2(acc[i][2], ap8[i], bp4[2]);
                fma2(acc[i][3], ap8[i], bp4[3]);
            }
        }
        if (more) {
            const int nbuf = buf ^ 1;
            float av[8] = {na0.x, na0.y, na0.z, na0.w, na1.x, na1.y, na1.z, na1.w};
#pragma unroll
            for (int i = 0; i < 8; i++) {
                float* asr = (float*)(smem + AS_OFF(nbuf) + (a_k0 + i) * 1024);
                *(unsigned long long*)(asr + 2 * a_co) = pack2(av[i], av[i]);
            }
            float* bsr = (float*)(smem + BS_OFF(nbuf) + b_k * 512);
            *(float4*)(bsr + b_j0)     = nb0;
            *(float4*)(bsr + b_j0 + 4) = nb1;
        }
        __syncthreads();
    }

    // epilogue: raw store to g_M[uv][co][j]
#pragma unroll
    for (int i = 0; i < 8; i++) {
        const int r = (i < 4) ? (4 * ty + i) : (64 + 4 * ty + (i - 4));
        float* mp = g_M + ((size_t)uv * G_TOT + gb + r) * J_PAD + jb;
        float v0, v1, v2, v3;
        unpack2(acc[i][0], v0, v1); unpack2(acc[i][1], v2, v3);
        *(float4*)(mp + tx * 4) = make_float4(v0, v1, v2, v3);
        unpack2(acc[i][2], v0, v1); unpack2(acc[i][3], v2, v3);
        *(float4*)(mp + 64 + tx * 4) = make_float4(v0, v1, v2, v3);
    }
}

// F(4,3) A^T-row combo applied to a 6-vector -> 4 outputs
#define ACOMBO(out, x0, x1, x2, x3, x4, x5) \
    out[0] = (x0) + (x1) + (x2) + (x3) + (x4); \
    out[1] = (x1) - (x2) + 2.0f*(x3) - 2.0f*(x4); \
    out[2] = (x1) + (x2) + 4.0f*(x3) + 4.0f*(x4); \
    out[3] = (x1) - (x2) + 8.0f*(x3) - 8.0f*(x4) + (x5);

// ---------------- kernel: inverse transform + BN + SiLU -> g_H[co][m] ----------------
__global__ void out_transform_kernel() {
    int idx = blockIdx.x * blockDim.x + threadIdx.x;      // 4608*240
    if (idx >= G_TOT * J_TOT) return;
    int co = idx / J_TOT, j = idx % J_TOT;
    int n = j / NT, t = j % NT;
    int ty = t / TX_T, tx = t % TX_T;
    size_t plane = (size_t)G_TOT * J_PAD;
    const float* mp = g_M + (size_t)co * J_PAD + j;
    float M[6][6];
#pragma unroll
    for (int uv = 0; uv < 36; uv++) M[uv / 6][uv % 6] = mp[(size_t)uv * plane];
    // T = A^T M : 4x6
    float T[4][6];
    {
        float col[4];
#pragma unroll
        for (int b = 0; b < 6; b++) {
            ACOMBO(col, M[0][b], M[1][b], M[2][b], M[3][b], M[4][b], M[5][b]);
#pragma unroll
            for (int a = 0; a < 4; a++) T[a][b] = col[a];
        }
    }
    const float sc = g_scale[co], sh = g_shift[co];
    float* hp = g_H + (size_t)co * M_TOT + n * POS + (4 * ty) * WF + 4 * tx;
#pragma unroll
    for (int a = 0; a < 4; a++) {
        float y[4];
        ACOMBO(y, T[a][0], T[a][1], T[a][2], T[a][3], T[a][4], T[a][5]);
        float4 o;
        float v;
        v = y[0] * sc + sh; o.x = v / (1.0f + expf(-v));
        v = y[1] * sc + sh; o.y = v / (1.0f + expf(-v));
        v = y[2] * sc + sh; o.z = v / (1.0f + expf(-v));
        v = y[3] * sc + sh; o.w = v / (1.0f + expf(-v));
        *(float4*)(hp + a * WF) = o;
    }
}

// ---------------- kernel 1: global-average pool + linear + single_out ----------------
__global__ void single_kernel(const float* __restrict__ f,
                              const float* __restrict__ linW,
                              const float* __restrict__ linb,
                              float* __restrict__ out) {
    const int n = blockIdx.x;
    const int c = threadIdx.x;                 // 576
    __shared__ float sf1[C_IN];
    __shared__ float slin[10];
    const float* p = f + ((size_t)n * C_IN + c) * POS;
    float s = 0.f;
#pragma unroll 4
    for (int i = 0; i < POS; i++) s += p[i];
    sf1[c] = s / 240.0f;
    __syncthreads();
    if (c < 10) {
        float a = linb[c];
        for (int k = 0; k < C_IN; k++) a += sf1[k] * linW[c * C_IN + k];
        slin[c] = a;
    }
    __syncthreads();
    if (c == 0) {
        const float eps = 1e-5f;
        float conf = clipf(sigm(slin[0]), eps, 1.0f - eps);
        int best = 0; float bv = slin[1];
        for (int i = 1; i < 5; i++) if (slin[1 + i] > bv) { bv = slin[1 + i]; best = i; }
        float dist = sigm(slin[6]) * 3.0f;
        float offv = tanhf(slin[7]);
        float sev  = clipf(sigm(slin[8]), eps, 1.0f - eps);
        float surf = clipf(sigm(slin[9]), eps, 1.0f - eps);
        float* o = out + n * 6;
        o[0] = conf; o[1] = (float)best; o[2] = dist; o[3] = offv; o[4] = sev; o[5] = surf;
    }
}

// ---------------- kernel 5: w2 reduction -> 14 maps ----------------
__constant__ int c_offs[9] = {0, 5, 6, 8, 10, 11, 12, 13, 14};
__global__ void maps_kernel(const float* __restrict__ w2, const float* __restrict__ b2) {
    const int head = blockIdx.y;
    const int o0 = c_offs[head], o1 = c_offs[head + 1];
    const int no = o1 - o0;
    __shared__ float sw2[5][C_IN];
    const int t = threadIdx.x;                 // 128
    for (int i = t; i < no * C_IN; i += 128) sw2[i / C_IN][i % C_IN] = w2[o0 * C_IN + i];
    __syncthreads();
    const int m = blockIdx.x * 128 + t;
    float acc[5] = {0.f, 0.f, 0.f, 0.f, 0.f};
    const float* hp = g_H + (size_t)head * C_IN * M_TOT + m;
#pragma unroll 4
    for (int c = 0; c < C_IN; c++) {
        float v = hp[(size_t)c * M_TOT];
#pragma unroll
        for (int o = 0; o < 5; o++)
            if (o < no) acc[o] += sw2[o][c] * v;
    }
#pragma unroll
    for (int o = 0; o < 5; o++)
        if (o < no) g_maps[(o0 + o) * M_TOT + m] = acc[o] + b2[o0 + o];
}

// ---------------- kernel 6: per-(n,class) top-20 ----------------
__global__ void topk_kernel() {
    const int n = blockIdx.x / 5, j = blockIdx.x % 5;
    const int t = threadIdx.x;                 // 256
    __shared__ float sc[256];
    __shared__ float rv[256];
    __shared__ int   ri[256];
    __shared__ float selv[20];
    __shared__ int   seli[20];

    float s = -1e30f;
    if (t < POS) {
        float heat = sigm(g_maps[j * M_TOT + n * POS + t]);
        float cf   = sigm(g_maps[5 * M_TOT + n * POS + t]);
        s = heat * cf;
    }
    sc[t] = s;
    __syncthreads();

    for (int r = 0; r < 20; r++) {
        rv[t] = sc[t]; ri[t] = t;
        __syncthreads();
#pragma unroll
        for (int off = 128; off > 0; off >>= 1) {
            if (t < off) {
                float v2 = rv[t + off]; int i2 = ri[t + off];
                if (v2 > rv[t] || (v2 == rv[t] && i2 < ri[t])) { rv[t] = v2; ri[t] = i2; }
            }
            __syncthreads();
        }
        if (t == 0) { selv[r] = rv[0]; seli[r] = ri[0]; sc[ri[0]] = -1e30f; }
        __syncthreads();
    }

    if (t < 20) {
        const int idx = seli[t];
        const float score = selv[t];
        const int base = n * POS + idx;
        float gx = sigm(g_maps[6  * M_TOT + base]);
        float gy = sigm(g_maps[7  * M_TOT + base]);
        float gw = sigm(g_maps[8  * M_TOT + base]);
        float gh = sigm(g_maps[9  * M_TOT + base]);
        float gd = sigm(g_maps[10 * M_TOT + base]) * 3.0f;
        float go = tanhf(g_maps[11 * M_TOT + base]);
        float gs = sigm(g_maps[12 * M_TOT + base]);
        float gf = sigm(g_maps[13 * M_TOT + base]);
        float xi = (float)(idx % WF);
        float yi = (float)(idx / WF);
        float cx = clipf(xi + gx, 0.f, (float)(WF - 1)) * 32.0f;
        float cy = clipf(yi + gy, 0.f, (float)(HF - 1)) * 32.0f;
        float bw = clipf(gw, 0.f, 1.f) * 640.0f;
        float bh = clipf(gh, 0.f, 1.f) * 384.0f;
        float x1 = clipf(cx - bw * 0.5f, 0.f, 639.0f);
        float y1 = clipf(cy - bh * 0.5f, 0.f, 383.0f);
        float x2 = clipf(cx + bw * 0.5f, 0.f, 639.0f);
        float y2 = clipf(cy + bh * 0.5f, 0.f, 383.0f);
        float* row = g_cand + ((size_t)n * 100 + j * 20 + t) * 10;
        row[0] = score; row[1] = (float)j; row[2] = gd; row[3] = go; row[4] = gs;
        row[5] = gf; row[6] = x1; row[7] = y1; row[8] = x2; row[9] = y2;
    }
}

// ---------------- kernel 7: stable sort by dist -> dets_out ----------------
__global__ void sort_out_kernel(float* __restrict__ out) {
    const int n = blockIdx.x;
    const int t = threadIdx.x;                 // 128
    __shared__ float d[100];
    if (t < 100) d[t] = g_cand[((size_t)n * 100 + t) * 10 + 2];
    __syncthreads();
    if (t < 100) {
        float di = d[t];
        int rank = 0;
        for (int k = 0; k < 100; k++) {
            float dk = d[k];
            rank += (dk < di) || (dk == di && k < t);
        }
        if (rank < 20) {
            float* dst = out + 96 + ((size_t)n * 20 + rank) * 10;
            const float* src = g_cand + ((size_t)n * 100 + t) * 10;
#pragma unroll
            for (int q = 0; q < 10; q++) dst[q] = src[q];
        }
    }
}

// ---------------- launch ----------------
extern "C" void kernel_launch(void* const* d_in, const int* in_sizes, int n_in,
                              void* d_out, int out_size) {
    const float* f    = (const float*)d_in[0];
    const float* w1   = (const float*)d_in[1];
    const float* bng  = (const float*)d_in[2];
    const float* bnb  = (const float*)d_in[3];
    const float* bnm  = (const float*)d_in[4];
    const float* bnv  = (const float*)d_in[5];
    const float* w2   = (const float*)d_in[6];
    const float* b2   = (const float*)d_in[7];
    const float* linW = (const float*)d_in[8];
    const float* linb = (const float*)d_in[9];
    float* out = (float*)d_out;

    single_kernel<<<NB, C_IN>>>(f, linW, linb, out);
    bn_prep_kernel<<<(G_TOT + 255) / 256, 256>>>(bng, bnb, bnm, bnv);
    wg_transform_kernel<<<(G_TOT * C_IN) / 256, 256>>>(w1);               // 10368 blocks
    in_transform_kernel<<<(NB * C_IN * NT + 255) / 256, 256>>>(f);        // 540 blocks
    dim3 gg(J_PAD / 128, G_TOT / 128, NUV);                               // (2, 36, 36)
    gemm_kernel<<<gg, 256, 49152>>>();
    out_transform_kernel<<<(G_TOT * J_TOT + 255) / 256, 256>>>();         // 4320 blocks
    dim3 mg(M_TOT / 128, 8);
    maps_kernel<<<mg, 128>>>(w2, b2);
    topk_kernel<<<NB * 5, 256>>>();
    sort_out_kernel<<<NB, 128>>>(out);
}

// round 13
// speedup vs baseline: 5.1986x; 1.7060x over previous
#include <cuda_runtime.h>
#include <cuda_bf16.h>
#include <math.h>
#include <cstdint>

// ---------------- problem constants ----------------
#define C_IN 576
#define HF   12
#define WF   20
#define NB   16
#define POS  240
#define M_TOT 3840                 // positions (16*240)
#define G_TOT 4608                 // 8*576 output channels
#define TY_T 3                     // winograd F(4,3) tile rows  (12/4)
#define TX_T 5                     // winograd F(4,3) tile cols  (20/4)
#define NT   15                    // tiles per image
#define J_TOT (NB*NT)              // 240
#define J_PAD 256
#define NUV  36                    // 6x6 transform plane count
#define KC   32                    // k per chunk
#define NCH  (C_IN/KC)             // 18 chunks

// ---------------- scratch (static device globals; zero-initialized) ----------------
__device__ __align__(16) __nv_bfloat16 g_Uh[(size_t)NUV * G_TOT * C_IN];  // ~191MB
__device__ __align__(16) __nv_bfloat16 g_Ul[(size_t)NUV * G_TOT * C_IN];  // ~191MB
__device__ __align__(16) __nv_bfloat16 g_Vh[(size_t)NUV * J_PAD * C_IN];  // ~10.6MB (pad rows stay 0)
__device__ __align__(16) __nv_bfloat16 g_Vl[(size_t)NUV * J_PAD * C_IN];
__device__ __align__(16) float g_M[(size_t)NUV * G_TOT * J_PAD];          // ~170MB
__device__ __align__(16) float g_H[(size_t)G_TOT * M_TOT];                // ~71MB
__device__ float g_scale[G_TOT];
__device__ float g_shift[G_TOT];
__device__ __align__(16) float g_maps[14 * M_TOT];
__device__ __align__(16) float g_cand[NB * 100 * 10];

// ---------------- helpers ----------------
__device__ __forceinline__ float sigm(float x) { return 1.0f / (1.0f + expf(-x)); }
__device__ __forceinline__ float clipf(float x, float lo, float hi) { return fminf(fmaxf(x, lo), hi); }

__device__ __forceinline__ void bf16_split(float x, __nv_bfloat16& hi, __nv_bfloat16& lo) {
    hi = __float2bfloat16_rn(x);
    lo = __float2bfloat16_rn(x - __bfloat162float(hi));
}

// bf16 m16n8k16 mma, fp32 accumulate
__device__ __forceinline__ void mma_bf16(float* c, const uint32_t* a, uint32_t b0, uint32_t b1) {
    asm volatile(
        "mma.sync.aligned.m16n8k16.row.col.f32.bf16.bf16.f32 "
        "{%0,%1,%2,%3}, {%4,%5,%6,%7}, {%8,%9}, {%0,%1,%2,%3};"
        : "+f"(c[0]), "+f"(c[1]), "+f"(c[2]), "+f"(c[3])
        : "r"(a[0]), "r"(a[1]), "r"(a[2]), "r"(a[3]), "r"(b0), "r"(b1));
}

// ---------------- kernel: BN fold ----------------
__global__ void bn_prep_kernel(const float* __restrict__ g, const float* __restrict__ b,
                               const float* __restrict__ m, const float* __restrict__ v) {
    int i = blockIdx.x * blockDim.x + threadIdx.x;
    if (i < G_TOT) {
        float sc = g[i] / sqrtf(v[i] + 1e-5f);
        g_scale[i] = sc;
        g_shift[i] = b[i] - m[i] * sc;
    }
}

// F(4,3) G-row combo applied to a 3-vector (a,b,c) -> 6 outputs
#define GCOMBO(out, a, b, c) \
    out[0] = 0.25f * (a); \
    out[1] = -(1.0f/6.0f) * ((a) + (b) + (c)); \
    out[2] = (1.0f/6.0f) * (-(a) + (b) - (c)); \
    out[3] = (1.0f/24.0f) * (a) + (1.0f/12.0f) * (b) + (1.0f/6.0f) * (c); \
    out[4] = (1.0f/24.0f) * (a) - (1.0f/12.0f) * (b) + (1.0f/6.0f) * (c); \
    out[5] = (c);

// ---------------- kernel: winograd F(4,3) weight transform -> split bf16 ----------------
__global__ void wg_transform_kernel(const float* __restrict__ w1) {
    int idx = blockIdx.x * blockDim.x + threadIdx.x;      // 4608*576
    int co = idx / C_IN, ci = idx % C_IN;
    const float* w = w1 + (size_t)idx * 9;
    float T[6][3];
    {
        float col[6];
#pragma unroll
        for (int c = 0; c < 3; c++) {
            GCOMBO(col, w[c], w[3 + c], w[6 + c]);
#pragma unroll
            for (int r = 0; r < 6; r++) T[r][c] = col[r];
        }
    }
    size_t plane = (size_t)G_TOT * C_IN;
    size_t off0 = (size_t)co * C_IN + ci;
#pragma unroll
    for (int r = 0; r < 6; r++) {
        float u[6];
        GCOMBO(u, T[r][0], T[r][1], T[r][2]);
#pragma unroll
        for (int c = 0; c < 6; c++) {
            __nv_bfloat16 hi, lo;
            bf16_split(u[c], hi, lo);
            size_t off = (size_t)(r * 6 + c) * plane + off0;
            g_Uh[off] = hi;
            g_Ul[off] = lo;
        }
    }
}

// F(4,3) B^T-row combo applied to a 6-vector -> 6 outputs
#define BCOMBO(out, x0, x1, x2, x3, x4, x5) \
    out[0] = 4.0f*(x0) - 5.0f*(x2) + (x4); \
    out[1] = -4.0f*(x1) - 4.0f*(x2) + (x3) + (x4); \
    out[2] =  4.0f*(x1) - 4.0f*(x2) - (x3) + (x4); \
    out[3] = -2.0f*(x1) - (x2) + 2.0f*(x3) + (x4); \
    out[4] =  2.0f*(x1) - (x2) - 2.0f*(x3) + (x4); \
    out[5] =  4.0f*(x1) - 5.0f*(x3) + (x5);

// ---------------- kernel: winograd input transform -> split bf16 [uv][j][ci] ----------------
__global__ void in_transform_kernel(const float* __restrict__ f) {
    int idx = blockIdx.x * blockDim.x + threadIdx.x;      // (16*15)*576, ci fastest
    if (idx >= NB * NT * C_IN) return;
    int j  = idx / C_IN;                                  // n*NT + t
    int ci = idx % C_IN;
    int n = j / NT, t = j % NT;
    int ty = t / TX_T, tx = t % TX_T;
    const float* fp = f + ((size_t)n * C_IN + ci) * POS;
    float X[6][6];
#pragma unroll
    for (int a = 0; a < 6; a++) {
        int iy = 4 * ty - 1 + a;
#pragma unroll
        for (int b = 0; b < 6; b++) {
            int ix = 4 * tx - 1 + b;
            X[a][b] = ((unsigned)iy < HF && (unsigned)ix < WF) ? fp[iy * WF + ix] : 0.f;
        }
    }
    float T[6][6];
    {
        float col[6];
#pragma unroll
        for (int b = 0; b < 6; b++) {
            BCOMBO(col, X[0][b], X[1][b], X[2][b], X[3][b], X[4][b], X[5][b]);
#pragma unroll
            for (int a = 0; a < 6; a++) T[a][b] = col[a];
        }
    }
    size_t base = (size_t)j * C_IN + ci;
    size_t plane = (size_t)J_PAD * C_IN;
#pragma unroll
    for (int a = 0; a < 6; a++) {
        float v[6];
        BCOMBO(v, T[a][0], T[a][1], T[a][2], T[a][3], T[a][4], T[a][5]);
#pragma unroll
        for (int b = 0; b < 6; b++) {
            __nv_bfloat16 hi, lo;
            bf16_split(v[b], hi, lo);
            size_t off = (size_t)(a * 6 + b) * plane + base;
            g_Vh[off] = hi;
            g_Vl[off] = lo;
        }
    }
}

// ---------------- tensor-core GEMM: bf16 3-term split, M_uv = U_uv x V_uv ----------------
// grid (2, 36, 36), 256 threads = 8 warps (4 m-warps x 2 n-warps), CTA tile 128co x 128j.
// SMEM per buffer: 4 tiles (Uh,Ul,Vh,Vl), each 128 rows x 32 bf16 padded to 80B/row = 10240B.
#define TILE_B   10240
#define BUF_B    40960
#define GEMM_SMEM (2*BUF_B)

__global__ __launch_bounds__(256, 1) void gemm_mma_kernel() {
    extern __shared__ char smem[];
    const int tid = threadIdx.x;
    const int wid = tid >> 5, lane = tid & 31;
    const int g = lane >> 2, tg = lane & 3;
    const int jb = blockIdx.x * 128;
    const int gb = blockIdx.y * 128;
    const int uv = blockIdx.z;
    const int wm = (wid & 3) * 32;            // warp co base within tile
    const int wn = (wid >> 2) * 64;           // warp j  base within tile

    const char* srcs[4];
    srcs[0] = (const char*)(g_Uh + ((size_t)uv * G_TOT + gb) * C_IN);
    srcs[1] = (const char*)(g_Ul + ((size_t)uv * G_TOT + gb) * C_IN);
    srcs[2] = (const char*)(g_Vh + ((size_t)uv * J_PAD + jb) * C_IN);
    srcs[3] = (const char*)(g_Vl + ((size_t)uv * J_PAD + jb) * C_IN);

    const int r0 = tid >> 2, s0 = (tid & 3);          // unit 0: rows 0..63
    const int r1 = (tid + 256) >> 2;                   // unit 1: rows 64..127

    // prologue: stage chunk 0 into buffer 0
#pragma unroll
    for (int tile = 0; tile < 4; tile++) {
        char* dp = smem + tile * TILE_B;
        *(uint4*)(dp + r0 * 80 + s0 * 16) = *(const uint4*)(srcs[tile] + (size_t)r0 * (C_IN * 2) + s0 * 16);
        *(uint4*)(dp + r1 * 80 + s0 * 16) = *(const uint4*)(srcs[tile] + (size_t)r1 * (C_IN * 2) + s0 * 16);
    }
    __syncthreads();

    float acc[2][8][4];
#pragma unroll
    for (int mt = 0; mt < 2; mt++)
#pragma unroll
        for (int nt = 0; nt < 8; nt++)
#pragma unroll
            for (int i = 0; i < 4; i++) acc[mt][nt][i] = 0.f;

    for (int c = 0; c < NCH; c++) {
        const int buf = c & 1;
        uint4 pre[4][2];
        const bool more = (c + 1 < NCH);
        if (more) {
#pragma unroll
            for (int tile = 0; tile < 4; tile++) {
                const char* sp = srcs[tile] + (c + 1) * (KC * 2);
                pre[tile][0] = *(const uint4*)(sp + (size_t)r0 * (C_IN * 2) + s0 * 16);
                pre[tile][1] = *(const uint4*)(sp + (size_t)r1 * (C_IN * 2) + s0 * 16);
            }
        }
        const char* Us = smem + buf * BUF_B;
        const char* Vs = Us + 2 * TILE_B;
#pragma unroll
        for (int kh = 0; kh < 2; kh++) {
            const int kbyte = kh * 32 + tg * 4;
            uint32_t ah[2][4], al[2][4];
#pragma unroll
            for (int mt = 0; mt < 2; mt++) {
                const char* ab = Us + (wm + mt * 16 + g) * 80 + kbyte;
                ah[mt][0] = *(const uint32_t*)(ab);
                ah[mt][1] = *(const uint32_t*)(ab + 8 * 80);
                ah[mt][2] = *(const uint32_t*)(ab + 16);
                ah[mt][3] = *(const uint32_t*)(ab + 8 * 80 + 16);
                al[mt][0] = *(const uint32_t*)(ab + TILE_B);
                al[mt][1] = *(const uint32_t*)(ab + TILE_B + 8 * 80);
                al[mt][2] = *(const uint32_t*)(ab + TILE_B + 16);
                al[mt][3] = *(const uint32_t*)(ab + TILE_B + 8 * 80 + 16);
            }
#pragma unroll
            for (int nt = 0; nt < 8; nt++) {
                const char* bb = Vs + (wn + nt * 8 + g) * 80 + kbyte;
                uint32_t bh0 = *(const uint32_t*)(bb);
                uint32_t bh1 = *(const uint32_t*)(bb + 16);
                uint32_t bl0 = *(const uint32_t*)(bb + TILE_B);
                uint32_t bl1 = *(const uint32_t*)(bb + TILE_B + 16);
#pragma unroll
                for (int mt = 0; mt < 2; mt++) {
                    mma_bf16(acc[mt][nt], ah[mt], bh0, bh1);
                    mma_bf16(acc[mt][nt], ah[mt], bl0, bl1);
                    mma_bf16(acc[mt][nt], al[mt], bh0, bh1);
                }
            }
        }
        if (more) {
            const int nbuf = buf ^ 1;
#pragma unroll
            for (int tile = 0; tile < 4; tile++) {
                char* dp = smem + nbuf * BUF_B + tile * TILE_B;
                *(uint4*)(dp + r0 * 80 + s0 * 16) = pre[tile][0];
                *(uint4*)(dp + r1 * 80 + s0 * 16) = pre[tile][1];
            }
        }
        __syncthreads();
    }

    // epilogue: store fp32 to g_M[uv][co][j]
    float* Mbase = g_M + (size_t)uv * G_TOT * J_PAD;
#pragma unroll
    for (int mt = 0; mt < 2; mt++) {
        const int row = gb + wm + mt * 16 + g;
#pragma unroll
        for (int nt = 0; nt < 8; nt++) {
            const int j0 = jb + wn + nt * 8 + 2 * tg;
            *(float2*)(Mbase + (size_t)row * J_PAD + j0)       = make_float2(acc[mt][nt][0], acc[mt][nt][1]);
            *(float2*)(Mbase + (size_t)(row + 8) * J_PAD + j0) = make_float2(acc[mt][nt][2], acc[mt][nt][3]);
        }
    }
}

// F(4,3) A^T-row combo applied to a 6-vector -> 4 outputs
#define ACOMBO(out, x0, x1, x2, x3, x4, x5) \
    out[0] = (x0) + (x1) + (x2) + (x3) + (x4); \
    out[1] = (x1) - (x2) + 2.0f*(x3) - 2.0f*(x4); \
    out[2] = (x1) + (x2) + 4.0f*(x3) + 4.0f*(x4); \
    out[3] = (x1) - (x2) + 8.0f*(x3) - 8.0f*(x4) + (x5);

// ---------------- kernel: inverse transform + BN + SiLU -> g_H[co][m] ----------------
__global__ void out_transform_kernel() {
    int idx = blockIdx.x * blockDim.x + threadIdx.x;      // 4608*240
    if (idx >= G_TOT * J_TOT) return;
    int co = idx / J_TOT, j = idx % J_TOT;
    int n = j / NT, t = j % NT;
    int ty = t / TX_T, tx = t % TX_T;
    size_t plane = (size_t)G_TOT * J_PAD;
    const float* mp = g_M + (size_t)co * J_PAD + j;
    float M[6][6];
#pragma unroll
    for (int uv = 0; uv < 36; uv++) M[uv / 6][uv % 6] = mp[(size_t)uv * plane];
    float T[4][6];
    {
        float col[4];
#pragma unroll
        for (int b = 0; b < 6; b++) {
            ACOMBO(col, M[0][b], M[1][b], M[2][b], M[3][b], M[4][b], M[5][b]);
#pragma unroll
            for (int a = 0; a < 4; a++) T[a][b] = col[a];
        }
    }
    const float sc = g_scale[co], sh = g_shift[co];
    float* hp = g_H + (size_t)co * M_TOT + n * POS + (4 * ty) * WF + 4 * tx;
#pragma unroll
    for (int a = 0; a < 4; a++) {
        float y[4];
        ACOMBO(y, T[a][0], T[a][1], T[a][2], T[a][3], T[a][4], T[a][5]);
        float4 o;
        float v;
        v = y[0] * sc + sh; o.x = v / (1.0f + expf(-v));
        v = y[1] * sc + sh; o.y = v / (1.0f + expf(-v));
        v = y[2] * sc + sh; o.z = v / (1.0f + expf(-v));
        v = y[3] * sc + sh; o.w = v / (1.0f + expf(-v));
        *(float4*)(hp + a * WF) = o;
    }
}

// ---------------- kernel 1: global-average pool + linear + single_out ----------------
__global__ void single_kernel(const float* __restrict__ f,
                              const float* __restrict__ linW,
                              const float* __restrict__ linb,
                              float* __restrict__ out) {
    const int n = blockIdx.x;
    const int c = threadIdx.x;                 // 576
    __shared__ float sf1[C_IN];
    __shared__ float slin[10];
    const float* p = f + ((size_t)n * C_IN + c) * POS;
    float s = 0.f;
#pragma unroll 4
    for (int i = 0; i < POS; i++) s += p[i];
    sf1[c] = s / 240.0f;
    __syncthreads();
    if (c < 10) {
        float a = linb[c];
        for (int k = 0; k < C_IN; k++) a += sf1[k] * linW[c * C_IN + k];
        slin[c] = a;
    }
    __syncthreads();
    if (c == 0) {
        const float eps = 1e-5f;
        float conf = clipf(sigm(slin[0]), eps, 1.0f - eps);
        int best = 0; float bv = slin[1];
        for (int i = 1; i < 5; i++) if (slin[1 + i] > bv) { bv = slin[1 + i]; best = i; }
        float dist = sigm(slin[6]) * 3.0f;
        float offv = tanhf(slin[7]);
        float sev  = clipf(sigm(slin[8]), eps, 1.0f - eps);
        float surf = clipf(sigm(slin[9]), eps, 1.0f - eps);
        float* o = out + n * 6;
        o[0] = conf; o[1] = (float)best; o[2] = dist; o[3] = offv; o[4] = sev; o[5] = surf;
    }
}

// ---------------- kernel 5: w2 reduction -> 14 maps ----------------
__constant__ int c_offs[9] = {0, 5, 6, 8, 10, 11, 12, 13, 14};
__global__ void maps_kernel(const float* __restrict__ w2, const float* __restrict__ b2) {
    const int head = blockIdx.y;
    const int o0 = c_offs[head], o1 = c_offs[head + 1];
    const int no = o1 - o0;
    __shared__ float sw2[5][C_IN];
    const int t = threadIdx.x;                 // 128
    for (int i = t; i < no * C_IN; i += 128) sw2[i / C_IN][i % C_IN] = w2[o0 * C_IN + i];
    __syncthreads();
    const int m = blockIdx.x * 128 + t;
    float acc[5] = {0.f, 0.f, 0.f, 0.f, 0.f};
    const float* hp = g_H + (size_t)head * C_IN * M_TOT + m;
#pragma unroll 4
    for (int c = 0; c < C_IN; c++) {
        float v = hp[(size_t)c * M_TOT];
#pragma unroll
        for (int o = 0; o < 5; o++)
            if (o < no) acc[o] += sw2[o][c] * v;
    }
#pragma unroll
    for (int o = 0; o < 5; o++)
        if (o < no) g_maps[(o0 + o) * M_TOT + m] = acc[o] + b2[o0 + o];
}

// ---------------- kernel 6: per-(n,class) top-20 ----------------
__global__ void topk_kernel() {
    const int n = blockIdx.x / 5, j = blockIdx.x % 5;
    const int t = threadIdx.x;                 // 256
    __shared__ float sc[256];
    __shared__ float rv[256];
    __shared__ int   ri[256];
    __shared__ float selv[20];
    __shared__ int   seli[20];

    float s = -1e30f;
    if (t < POS) {
        float heat = sigm(g_maps[j * M_TOT + n * POS + t]);
        float cf   = sigm(g_maps[5 * M_TOT + n * POS + t]);
        s = heat * cf;
    }
    sc[t] = s;
    __syncthreads();

    for (int r = 0; r < 20; r++) {
        rv[t] = sc[t]; ri[t] = t;
        __syncthreads();
#pragma unroll
        for (int off = 128; off > 0; off >>= 1) {
            if (t < off) {
                float v2 = rv[t + off]; int i2 = ri[t + off];
                if (v2 > rv[t] || (v2 == rv[t] && i2 < ri[t])) { rv[t] = v2; ri[t] = i2; }
            }
            __syncthreads();
        }
        if (t == 0) { selv[r] = rv[0]; seli[r] = ri[0]; sc[ri[0]] = -1e30f; }
        __syncthreads();
    }

    if (t < 20) {
        const int idx = seli[t];
        const float score = selv[t];
        const int base = n * POS + idx;
        float gx = sigm(g_maps[6  * M_TOT + base]);
        float gy = sigm(g_maps[7  * M_TOT + base]);
        float gw = sigm(g_maps[8  * M_TOT + base]);
        float gh = sigm(g_maps[9  * M_TOT + base]);
        float gd = sigm(g_maps[10 * M_TOT + base]) * 3.0f;
        float go = tanhf(g_maps[11 * M_TOT + base]);
        float gs = sigm(g_maps[12 * M_TOT + base]);
        float gf = sigm(g_maps[13 * M_TOT + base]);
        float xi = (float)(idx % WF);
        float yi = (float)(idx / WF);
        float cx = clipf(xi + gx, 0.f, (float)(WF - 1)) * 32.0f;
        float cy = clipf(yi + gy, 0.f, (float)(HF - 1)) * 32.0f;
        float bw = clipf(gw, 0.f, 1.f) * 640.0f;
        float bh = clipf(gh, 0.f, 1.f) * 384.0f;
        float x1 = clipf(cx - bw * 0.5f, 0.f, 639.0f);
        float y1 = clipf(cy - bh * 0.5f, 0.f, 383.0f);
        float x2 = clipf(cx + bw * 0.5f, 0.f, 639.0f);
        float y2 = clipf(cy + bh * 0.5f, 0.f, 383.0f);
        float* row = g_cand + ((size_t)n * 100 + j * 20 + t) * 10;
        row[0] = score; row[1] = (float)j; row[2] = gd; row[3] = go; row[4] = gs;
        row[5] = gf; row[6] = x1; row[7] = y1; row[8] = x2; row[9] = y2;
    }
}

// ---------------- kernel 7: stable sort by dist -> dets_out ----------------
__global__ void sort_out_kernel(float* __restrict__ out) {
    const int n = blockIdx.x;
    const int t = threadIdx.x;                 // 128
    __shared__ float d[100];
    if (t < 100) d[t] = g_cand[((size_t)n * 100 + t) * 10 + 2];
    __syncthreads();
    if (t < 100) {
        float di = d[t];
        int rank = 0;
        for (int k = 0; k < 100; k++) {
            float dk = d[k];
            rank += (dk < di) || (dk == di && k < t);
        }
        if (rank < 20) {
            float* dst = out + 96 + ((size_t)n * 20 + rank) * 10;
            const float* src = g_cand + ((size_t)n * 100 + t) * 10;
#pragma unroll
            for (int q = 0; q < 10; q++) dst[q] = src[q];
        }
    }
}

// ---------------- launch ----------------
extern "C" void kernel_launch(void* const* d_in, const int* in_sizes, int n_in,
                              void* d_out, int out_size) {
    const float* f    = (const float*)d_in[0];
    const float* w1   = (const float*)d_in[1];
    const float* bng  = (const float*)d_in[2];
    const float* bnb  = (const float*)d_in[3];
    const float* bnm  = (const float*)d_in[4];
    const float* bnv  = (const float*)d_in[5];
    const float* w2   = (const float*)d_in[6];
    const float* b2   = (const float*)d_in[7];
    const float* linW = (const float*)d_in[8];
    const float* linb = (const float*)d_in[9];
    float* out = (float*)d_out;

    cudaFuncSetAttribute(gemm_mma_kernel, cudaFuncAttributeMaxDynamicSharedMemorySize, GEMM_SMEM);

    single_kernel<<<NB, C_IN>>>(f, linW, linb, out);
    bn_prep_kernel<<<(G_TOT + 255) / 256, 256>>>(bng, bnb, bnm, bnv);
    wg_transform_kernel<<<(G_TOT * C_IN) / 256, 256>>>(w1);               // 10368 blocks
    in_transform_kernel<<<(NB * NT * C_IN + 255) / 256, 256>>>(f);        // 540 blocks
    dim3 gg(J_PAD / 128, G_TOT / 128, NUV);                               // (2, 36, 36)
    gemm_mma_kernel<<<gg, 256, GEMM_SMEM>>>();
    out_transform_kernel<<<(G_TOT * J_TOT + 255) / 256, 256>>>();         // 4320 blocks
    dim3 mg(M_TOT / 128, 8);
    maps_kernel<<<mg, 128>>>(w2, b2);
    topk_kernel<<<NB * 5, 256>>>();
    sort_out_kernel<<<NB, 128>>>(out);
}

// round 14
// speedup vs baseline: 5.7911x; 1.1140x over previous
#include <cuda_runtime.h>
#include <cuda_bf16.h>
#include <math.h>
#include <cstdint>

// ---------------- problem constants ----------------
#define C_IN 576
#define HF   12
#define WF   20
#define NB   16
#define POS  240
#define M_TOT 3840                 // positions (16*240)
#define G_TOT 4608                 // 8*576 output channels
#define TY_T 3                     // winograd F(4,3) tile rows  (12/4)
#define TX_T 5                     // winograd F(4,3) tile cols  (20/4)
#define NT   15                    // tiles per image
#define J_TOT (NB*NT)              // 240
#define J_PAD 256
#define NUV  36                    // 6x6 transform plane count
#define KC   32                    // k per chunk
#define NCH  (C_IN/KC)             // 18 chunks

// ---------------- scratch (static device globals; zero-initialized) ----------------
__device__ __align__(16) __nv_bfloat16 g_Uh[(size_t)NUV * G_TOT * C_IN];  // ~191MB
__device__ __align__(16) __nv_bfloat16 g_Ul[(size_t)NUV * G_TOT * C_IN];  // ~191MB
__device__ __align__(16) __nv_bfloat16 g_Vh[(size_t)NUV * J_PAD * C_IN];  // ~10.6MB (pad rows stay 0)
__device__ __align__(16) __nv_bfloat16 g_Vl[(size_t)NUV * J_PAD * C_IN];
__device__ __align__(16) float g_M[(size_t)NUV * G_TOT * J_PAD];          // ~170MB
__device__ __align__(16) float g_H[(size_t)G_TOT * M_TOT];                // ~71MB
__device__ float g_scale[G_TOT];
__device__ float g_shift[G_TOT];
__device__ __align__(16) float g_maps[14 * M_TOT];
__device__ __align__(16) float g_cand[NB * 100 * 10];

// ---------------- helpers ----------------
__device__ __forceinline__ float sigm(float x) { return 1.0f / (1.0f + expf(-x)); }
__device__ __forceinline__ float clipf(float x, float lo, float hi) { return fminf(fmaxf(x, lo), hi); }

__device__ __forceinline__ void bf16_split(float x, __nv_bfloat16& hi, __nv_bfloat16& lo) {
    hi = __float2bfloat16_rn(x);
    lo = __float2bfloat16_rn(x - __bfloat162float(hi));
}

// bf16 m16n8k16 mma, fp32 accumulate
__device__ __forceinline__ void mma_bf16(float* c, const uint32_t* a, uint32_t b0, uint32_t b1) {
    asm volatile(
        "mma.sync.aligned.m16n8k16.row.col.f32.bf16.bf16.f32 "
        "{%0,%1,%2,%3}, {%4,%5,%6,%7}, {%8,%9}, {%0,%1,%2,%3};"
        : "+f"(c[0]), "+f"(c[1]), "+f"(c[2]), "+f"(c[3])
        : "r"(a[0]), "r"(a[1]), "r"(a[2]), "r"(a[3]), "r"(b0), "r"(b1));
}

__device__ __forceinline__ void ldmatrix_x4(uint32_t* r, uint32_t addr) {
    asm volatile("ldmatrix.sync.aligned.m8n8.x4.shared.b16 {%0,%1,%2,%3}, [%4];"
        : "=r"(r[0]), "=r"(r[1]), "=r"(r[2]), "=r"(r[3]) : "r"(addr));
}

__device__ __forceinline__ void cp_async16(uint32_t dst, const void* src) {
    asm volatile("cp.async.cg.shared.global [%0], [%1], 16;" :: "r"(dst), "l"(src));
}

// ---------------- kernel: BN fold ----------------
__global__ void bn_prep_kernel(const float* __restrict__ g, const float* __restrict__ b,
                               const float* __restrict__ m, const float* __restrict__ v) {
    int i = blockIdx.x * blockDim.x + threadIdx.x;
    if (i < G_TOT) {
        float sc = g[i] / sqrtf(v[i] + 1e-5f);
        g_scale[i] = sc;
        g_shift[i] = b[i] - m[i] * sc;
    }
}

// F(4,3) G-row combo applied to a 3-vector (a,b,c) -> 6 outputs
#define GCOMBO(out, a, b, c) \
    out[0] = 0.25f * (a); \
    out[1] = -(1.0f/6.0f) * ((a) + (b) + (c)); \
    out[2] = (1.0f/6.0f) * (-(a) + (b) - (c)); \
    out[3] = (1.0f/24.0f) * (a) + (1.0f/12.0f) * (b) + (1.0f/6.0f) * (c); \
    out[4] = (1.0f/24.0f) * (a) - (1.0f/12.0f) * (b) + (1.0f/6.0f) * (c); \
    out[5] = (c);

// ---------------- kernel: winograd F(4,3) weight transform -> split bf16 ----------------
__global__ void wg_transform_kernel(const float* __restrict__ w1) {
    int idx = blockIdx.x * blockDim.x + threadIdx.x;      // 4608*576
    int co = idx / C_IN, ci = idx % C_IN;
    const float* w = w1 + (size_t)idx * 9;
    float T[6][3];
    {
        float col[6];
#pragma unroll
        for (int c = 0; c < 3; c++) {
            GCOMBO(col, w[c], w[3 + c], w[6 + c]);
#pragma unroll
            for (int r = 0; r < 6; r++) T[r][c] = col[r];
        }
    }
    size_t plane = (size_t)G_TOT * C_IN;
    size_t off0 = (size_t)co * C_IN + ci;
#pragma unroll
    for (int r = 0; r < 6; r++) {
        float u[6];
        GCOMBO(u, T[r][0], T[r][1], T[r][2]);
#pragma unroll
        for (int c = 0; c < 6; c++) {
            __nv_bfloat16 hi, lo;
            bf16_split(u[c], hi, lo);
            size_t off = (size_t)(r * 6 + c) * plane + off0;
            g_Uh[off] = hi;
            g_Ul[off] = lo;
        }
    }
}

// F(4,3) B^T-row combo applied to a 6-vector -> 6 outputs
#define BCOMBO(out, x0, x1, x2, x3, x4, x5) \
    out[0] = 4.0f*(x0) - 5.0f*(x2) + (x4); \
    out[1] = -4.0f*(x1) - 4.0f*(x2) + (x3) + (x4); \
    out[2] =  4.0f*(x1) - 4.0f*(x2) - (x3) + (x4); \
    out[3] = -2.0f*(x1) - (x2) + 2.0f*(x3) + (x4); \
    out[4] =  2.0f*(x1) - (x2) - 2.0f*(x3) + (x4); \
    out[5] =  4.0f*(x1) - 5.0f*(x3) + (x5);

// ---------------- kernel: winograd input transform -> split bf16 [uv][j][ci] ----------------
__global__ void in_transform_kernel(const float* __restrict__ f) {
    int idx = blockIdx.x * blockDim.x + threadIdx.x;      // (16*15)*576, ci fastest
    if (idx >= NB * NT * C_IN) return;
    int j  = idx / C_IN;                                  // n*NT + t
    int ci = idx % C_IN;
    int n = j / NT, t = j % NT;
    int ty = t / TX_T, tx = t % TX_T;
    const float* fp = f + ((size_t)n * C_IN + ci) * POS;
    float X[6][6];
#pragma unroll
    for (int a = 0; a < 6; a++) {
        int iy = 4 * ty - 1 + a;
#pragma unroll
        for (int b = 0; b < 6; b++) {
            int ix = 4 * tx - 1 + b;
            X[a][b] = ((unsigned)iy < HF && (unsigned)ix < WF) ? fp[iy * WF + ix] : 0.f;
        }
    }
    float T[6][6];
    {
        float col[6];
#pragma unroll
        for (int b = 0; b < 6; b++) {
            BCOMBO(col, X[0][b], X[1][b], X[2][b], X[3][b], X[4][b], X[5][b]);
#pragma unroll
            for (int a = 0; a < 6; a++) T[a][b] = col[a];
        }
    }
    size_t base = (size_t)j * C_IN + ci;
    size_t plane = (size_t)J_PAD * C_IN;
#pragma unroll
    for (int a = 0; a < 6; a++) {
        float v[6];
        BCOMBO(v, T[a][0], T[a][1], T[a][2], T[a][3], T[a][4], T[a][5]);
#pragma unroll
        for (int b = 0; b < 6; b++) {
            __nv_bfloat16 hi, lo;
            bf16_split(v[b], hi, lo);
            size_t off = (size_t)(a * 6 + b) * plane + base;
            g_Vh[off] = hi;
            g_Vl[off] = lo;
        }
    }
}

// ---------------- tensor-core GEMM: bf16 3-term split, M_uv = U_uv x V_uv ----------------
// grid (2, 36, 36), 256 threads = 8 warps (4 m-warps x 2 n-warps), CTA tile 128co x 128j.
// SMEM per buffer: 4 tiles (Uh,Ul,Vh,Vl), each 128 rows x 32 bf16 padded to 80B/row.
// cp.async staging + ldmatrix fragments, 2 CTAs/SM.
#define TILE_B   10240
#define BUF_B    40960
#define GEMM_SMEM (2*BUF_B)

__global__ __launch_bounds__(256, 2) void gemm_mma_kernel() {
    extern __shared__ char smem[];
    const uint32_t sbase = (uint32_t)__cvta_generic_to_shared(smem);
    const int tid = threadIdx.x;
    const int wid = tid >> 5, lane = tid & 31;
    const int g = lane >> 2, tg = lane & 3;
    const int jb = blockIdx.x * 128;
    const int gb = blockIdx.y * 128;
    const int uv = blockIdx.z;
    const int wm = (wid & 3) * 32;            // warp co base within tile
    const int wn = (wid >> 2) * 64;           // warp j  base within tile

    const char* srcs[4];
    srcs[0] = (const char*)(g_Uh + ((size_t)uv * G_TOT + gb) * C_IN);
    srcs[1] = (const char*)(g_Ul + ((size_t)uv * G_TOT + gb) * C_IN);
    srcs[2] = (const char*)(g_Vh + ((size_t)uv * J_PAD + jb) * C_IN);
    srcs[3] = (const char*)(g_Vl + ((size_t)uv * J_PAD + jb) * C_IN);

    const int r0 = tid >> 2, s0 = (tid & 3);          // unit 0: rows 0..63
    const int r1 = r0 + 64;                            // unit 1: rows 64..127

    // ldmatrix lane address components
    const int q = lane >> 3;
    const int a_row = (lane & 7) + ((q & 1) << 3);     // rows 0..15
    const int a_byte = (q >> 1) << 4;                  // 0 or 16
    const int b_row = lane & 7;
    const int b_byte = (q & 1) << 4;                   // 0 or 16
    const int b_sel = q >> 1;                          // which nt of the pair

    // staging: chunk c -> buffer buf (cp.async, 16B x 8 per thread)
    auto stage = [&](int c, int buf) {
#pragma unroll
        for (int tile = 0; tile < 4; tile++) {
            uint32_t dp = sbase + buf * BUF_B + tile * TILE_B;
            const char* sp = srcs[tile] + c * (KC * 2);
            cp_async16(dp + r0 * 80 + s0 * 16, sp + (size_t)r0 * (C_IN * 2) + s0 * 16);
            cp_async16(dp + r1 * 80 + s0 * 16, sp + (size_t)r1 * (C_IN * 2) + s0 * 16);
        }
        asm volatile("cp.async.commit_group;" ::: "memory");
    };

    stage(0, 0);
    asm volatile("cp.async.wait_group 0;" ::: "memory");
    __syncthreads();

    float acc[2][8][4];
#pragma unroll
    for (int mt = 0; mt < 2; mt++)
#pragma unroll
        for (int nt = 0; nt < 8; nt++)
#pragma unroll
            for (int i = 0; i < 4; i++) acc[mt][nt][i] = 0.f;

    for (int c = 0; c < NCH; c++) {
        const int buf = c & 1;
        const bool more = (c + 1 < NCH);
        if (more) stage(c + 1, buf ^ 1);

        const uint32_t Us = sbase + buf * BUF_B;
        const uint32_t Vs = Us + 2 * TILE_B;
#pragma unroll
        for (int kh = 0; kh < 2; kh++) {
            uint32_t ah[2][4], al[2][4];
#pragma unroll
            for (int mt = 0; mt < 2; mt++) {
                uint32_t abase = Us + (wm + mt * 16 + a_row) * 80 + kh * 32 + a_byte;
                ldmatrix_x4(ah[mt], abase);
                ldmatrix_x4(al[mt], abase + TILE_B);
            }
#pragma unroll
            for (int pr = 0; pr < 4; pr++) {
                uint32_t bbase = Vs + (wn + (2 * pr + b_sel) * 8 + b_row) * 80 + kh * 32 + b_byte;
                uint32_t bh[4], bl[4];
                ldmatrix_x4(bh, bbase);
                ldmatrix_x4(bl, bbase + TILE_B);
#pragma unroll
                for (int half = 0; half < 2; half++) {
                    const int nt = 2 * pr + half;
                    uint32_t h0 = bh[2 * half], h1 = bh[2 * half + 1];
                    uint32_t l0 = bl[2 * half], l1 = bl[2 * half + 1];
#pragma unroll
                    for (int mt = 0; mt < 2; mt++) {
                        mma_bf16(acc[mt][nt], ah[mt], h0, h1);
                        mma_bf16(acc[mt][nt], ah[mt], l0, l1);
                        mma_bf16(acc[mt][nt], al[mt], h0, h1);
                    }
                }
            }
        }
        if (more) asm volatile("cp.async.wait_group 0;" ::: "memory");
        __syncthreads();
    }

    // epilogue: store fp32 to g_M[uv][co][j]
    float* Mbase = g_M + (size_t)uv * G_TOT * J_PAD;
#pragma unroll
    for (int mt = 0; mt < 2; mt++) {
        const int row = gb + wm + mt * 16 + g;
#pragma unroll
        for (int nt = 0; nt < 8; nt++) {
            const int j0 = jb + wn + nt * 8 + 2 * tg;
            *(float2*)(Mbase + (size_t)row * J_PAD + j0)       = make_float2(acc[mt][nt][0], acc[mt][nt][1]);
            *(float2*)(Mbase + (size_t)(row + 8) * J_PAD + j0) = make_float2(acc[mt][nt][2], acc[mt][nt][3]);
        }
    }
}

// F(4,3) A^T-row combo applied to a 6-vector -> 4 outputs
#define ACOMBO(out, x0, x1, x2, x3, x4, x5) \
    out[0] = (x0) + (x1) + (x2) + (x3) + (x4); \
    out[1] = (x1) - (x2) + 2.0f*(x3) - 2.0f*(x4); \
    out[2] = (x1) + (x2) + 4.0f*(x3) + 4.0f*(x4); \
    out[3] = (x1) - (x2) + 8.0f*(x3) - 8.0f*(x4) + (x5);

// ---------------- kernel: inverse transform + BN + SiLU -> g_H[co][m] ----------------
__global__ void out_transform_kernel() {
    int idx = blockIdx.x * blockDim.x + threadIdx.x;      // 4608*240
    if (idx >= G_TOT * J_TOT) return;
    int co = idx / J_TOT, j = idx % J_TOT;
    int n = j / NT, t = j % NT;
    int ty = t / TX_T, tx = t % TX_T;
    size_t plane = (size_t)G_TOT * J_PAD;
    const float* mp = g_M + (size_t)co * J_PAD + j;
    float M[6][6];
#pragma unroll
    for (int uv = 0; uv < 36; uv++) M[uv / 6][uv % 6] = mp[(size_t)uv * plane];
    float T[4][6];
    {
        float col[4];
#pragma unroll
        for (int b = 0; b < 6; b++) {
            ACOMBO(col, M[0][b], M[1][b], M[2][b], M[3][b], M[4][b], M[5][b]);
#pragma unroll
            for (int a = 0; a < 4; a++) T[a][b] = col[a];
        }
    }
    const float sc = g_scale[co], sh = g_shift[co];
    float* hp = g_H + (size_t)co * M_TOT + n * POS + (4 * ty) * WF + 4 * tx;
#pragma unroll
    for (int a = 0; a < 4; a++) {
        float y[4];
        ACOMBO(y, T[a][0], T[a][1], T[a][2], T[a][3], T[a][4], T[a][5]);
        float4 o;
        float v;
        v = y[0] * sc + sh; o.x = v / (1.0f + expf(-v));
        v = y[1] * sc + sh; o.y = v / (1.0f + expf(-v));
        v = y[2] * sc + sh; o.z = v / (1.0f + expf(-v));
        v = y[3] * sc + sh; o.w = v / (1.0f + expf(-v));
        *(float4*)(hp + a * WF) = o;
    }
}

// ---------------- kernel 1: global-average pool + linear + single_out ----------------
__global__ void single_kernel(const float* __restrict__ f,
                              const float* __restrict__ linW,
                              const float* __restrict__ linb,
                              float* __restrict__ out) {
    const int n = blockIdx.x;
    const int c = threadIdx.x;                 // 576
    __shared__ float sf1[C_IN];
    __shared__ float slin[10];
    const float* p = f + ((size_t)n * C_IN + c) * POS;
    float s = 0.f;
#pragma unroll 4
    for (int i = 0; i < POS; i++) s += p[i];
    sf1[c] = s / 240.0f;
    __syncthreads();
    if (c < 10) {
        float a = linb[c];
        for (int k = 0; k < C_IN; k++) a += sf1[k] * linW[c * C_IN + k];
        slin[c] = a;
    }
    __syncthreads();
    if (c == 0) {
        const float eps = 1e-5f;
        float conf = clipf(sigm(slin[0]), eps, 1.0f - eps);
        int best = 0; float bv = slin[1];
        for (int i = 1; i < 5; i++) if (slin[1 + i] > bv) { bv = slin[1 + i]; best = i; }
        float dist = sigm(slin[6]) * 3.0f;
        float offv = tanhf(slin[7]);
        float sev  = clipf(sigm(slin[8]), eps, 1.0f - eps);
        float surf = clipf(sigm(slin[9]), eps, 1.0f - eps);
        float* o = out + n * 6;
        o[0] = conf; o[1] = (float)best; o[2] = dist; o[3] = offv; o[4] = sev; o[5] = surf;
    }
}

// ---------------- kernel 5: w2 reduction -> 14 maps ----------------
__constant__ int c_offs[9] = {0, 5, 6, 8, 10, 11, 12, 13, 14};
__global__ void maps_kernel(const float* __restrict__ w2, const float* __restrict__ b2) {
    const int head = blockIdx.y;
    const int o0 = c_offs[head], o1 = c_offs[head + 1];
    const int no = o1 - o0;
    __shared__ float sw2[5][C_IN];
    const int t = threadIdx.x;                 // 128
    for (int i = t; i < no * C_IN; i += 128) sw2[i / C_IN][i % C_IN] = w2[o0 * C_IN + i];
    __syncthreads();
    const int m = blockIdx.x * 128 + t;
    float acc[5] = {0.f, 0.f, 0.f, 0.f, 0.f};
    const float* hp = g_H + (size_t)head * C_IN * M_TOT + m;
#pragma unroll 4
    for (int c = 0; c < C_IN; c++) {
        float v = hp[(size_t)c * M_TOT];
#pragma unroll
        for (int o = 0; o < 5; o++)
            if (o < no) acc[o] += sw2[o][c] * v;
    }
#pragma unroll
    for (int o = 0; o < 5; o++)
        if (o < no) g_maps[(o0 + o) * M_TOT + m] = acc[o] + b2[o0 + o];
}

// ---------------- kernel 6: per-(n,class) top-20 ----------------
__global__ void topk_kernel() {
    const int n = blockIdx.x / 5, j = blockIdx.x % 5;
    const int t = threadIdx.x;                 // 256
    __shared__ float sc[256];
    __shared__ float rv[256];
    __shared__ int   ri[256];
    __shared__ float selv[20];
    __shared__ int   seli[20];

    float s = -1e30f;
    if (t < POS) {
        float heat = sigm(g_maps[j * M_TOT + n * POS + t]);
        float cf   = sigm(g_maps[5 * M_TOT + n * POS + t]);
        s = heat * cf;
    }
    sc[t] = s;
    __syncthreads();

    for (int r = 0; r < 20; r++) {
        rv[t] = sc[t]; ri[t] = t;
        __syncthreads();
#pragma unroll
        for (int off = 128; off > 0; off >>= 1) {
            if (t < off) {
                float v2 = rv[t + off]; int i2 = ri[t + off];
                if (v2 > rv[t] || (v2 == rv[t] && i2 < ri[t])) { rv[t] = v2; ri[t] = i2; }
            }
            __syncthreads();
        }
        if (t == 0) { selv[r] = rv[0]; seli[r] = ri[0]; sc[ri[0]] = -1e30f; }
        __syncthreads();
    }

    if (t < 20) {
        const int idx = seli[t];
        const float score = selv[t];
        const int base = n * POS + idx;
        float gx = sigm(g_maps[6  * M_TOT + base]);
        float gy = sigm(g_maps[7  * M_TOT + base]);
        float gw = sigm(g_maps[8  * M_TOT + base]);
        float gh = sigm(g_maps[9  * M_TOT + base]);
        float gd = sigm(g_maps[10 * M_TOT + base]) * 3.0f;
        float go = tanhf(g_maps[11 * M_TOT + base]);
        float gs = sigm(g_maps[12 * M_TOT + base]);
        float gf = sigm(g_maps[13 * M_TOT + base]);
        float xi = (float)(idx % WF);
        float yi = (float)(idx / WF);
        float cx = clipf(xi + gx, 0.f, (float)(WF - 1)) * 32.0f;
        float cy = clipf(yi + gy, 0.f, (float)(HF - 1)) * 32.0f;
        float bw = clipf(gw, 0.f, 1.f) * 640.0f;
        float bh = clipf(gh, 0.f, 1.f) * 384.0f;
        float x1 = clipf(cx - bw * 0.5f, 0.f, 639.0f);
        float y1 = clipf(cy - bh * 0.5f, 0.f, 383.0f);
        float x2 = clipf(cx + bw * 0.5f, 0.f, 639.0f);
        float y2 = clipf(cy + bh * 0.5f, 0.f, 383.0f);
        float* row = g_cand + ((size_t)n * 100 + j * 20 + t) * 10;
        row[0] = score; row[1] = (float)j; row[2] = gd; row[3] = go; row[4] = gs;
        row[5] = gf; row[6] = x1; row[7] = y1; row[8] = x2; row[9] = y2;
    }
}

// ---------------- kernel 7: stable sort by dist -> dets_out ----------------
__global__ void sort_out_kernel(float* __restrict__ out) {
    const int n = blockIdx.x;
    const int t = threadIdx.x;                 // 128
    __shared__ float d[100];
    if (t < 100) d[t] = g_cand[((size_t)n * 100 + t) * 10 + 2];
    __syncthreads();
    if (t < 100) {
        float di = d[t];
        int rank = 0;
        for (int k = 0; k < 100; k++) {
            float dk = d[k];
            rank += (dk < di) || (dk == di && k < t);
        }
        if (rank < 20) {
            float* dst = out + 96 + ((size_t)n * 20 + rank) * 10;
            const float* src = g_cand + ((size_t)n * 100 + t) * 10;
#pragma unroll
            for (int q = 0; q < 10; q++) dst[q] = src[q];
        }
    }
}

// ---------------- launch ----------------
extern "C" void kernel_launch(void* const* d_in, const int* in_sizes, int n_in,
                              void* d_out, int out_size) {
    const float* f    = (const float*)d_in[0];
    const float* w1   = (const float*)d_in[1];
    const float* bng  = (const float*)d_in[2];
    const float* bnb  = (const float*)d_in[3];
    const float* bnm  = (const float*)d_in[4];
    const float* bnv  = (const float*)d_in[5];
    const float* w2   = (const float*)d_in[6];
    const float* b2   = (const float*)d_in[7];
    const float* linW = (const float*)d_in[8];
    const float* linb = (const float*)d_in[9];
    float* out = (float*)d_out;

    cudaFuncSetAttribute(gemm_mma_kernel, cudaFuncAttributeMaxDynamicSharedMemorySize, GEMM_SMEM);

    single_kernel<<<NB, C_IN>>>(f, linW, linb, out);
    bn_prep_kernel<<<(G_TOT + 255) / 256, 256>>>(bng, bnb, bnm, bnv);
    wg_transform_kernel<<<(G_TOT * C_IN) / 256, 256>>>(w1);               // 10368 blocks
    in_transform_kernel<<<(NB * NT * C_IN + 255) / 256, 256>>>(f);        // 540 blocks
    dim3 gg(J_PAD / 128, G_TOT / 128, NUV);                               // (2, 36, 36)
    gemm_mma_kernel<<<gg, 256, GEMM_SMEM>>>();
    out_transform_kernel<<<(G_TOT * J_TOT + 255) / 256, 256>>>();         // 4320 blocks
    dim3 mg(M_TOT / 128, 8);
    maps_kernel<<<mg, 128>>>(w2, b2);
    topk_kernel<<<NB * 5, 256>>>();
    sort_out_kernel<<<NB, 128>>>(out);
}